// round 11
// baseline (speedup 1.0000x reference)
#include <cuda_runtime.h>
#include <mma.h>
#include <math.h>
#include <stdint.h>
#include <cuda_fp16.h>

using namespace nvcuda;

#define GRIDN 16
#define NN 256
#define DD 64
#define BB 4096
#define FF 512
#define HH 16384
#define CC 1000
#define CPAD 1024

// ---------------- scratch ----------------------------------------------------
__device__ __half g_nodes_h[(size_t)BB * HH];  // agg+bias, fp16 (128 MB)
__device__ float g_xr[(size_t)BB * FF];        // x rounded to tf32
__device__ float g_win2[(size_t)HH * FF];      // adj-folded W_in (tf32-rounded)
__device__ float g_bin2[HH];                   // folded b_in
__device__ float g_w[(size_t)BB * CPAD];       // softmax weights (tf32-rounded)
__device__ float g_mmat[(size_t)CC * CPAD];    // folded basis x W_out (tf32-rounded)
__device__ float g_adjw[NN * 4];
__device__ int   g_adjn[NN * 4];
__device__ float g_K[4 * DD];

__device__ __forceinline__ float sigmoidf_(float x) { return 1.0f / (1.0f + expf(-x)); }
__device__ __forceinline__ float clip3(float x) { return fminf(fmaxf(x, -3.0f), 3.0f); }

// ---------------- prep: adjacency rows + K = basis @ k_w^T + k_b ------------
__global__ void prep_kernel(const float* __restrict__ adjw,
                            const float* __restrict__ k_w,
                            const float* __restrict__ k_b,
                            const float* __restrict__ basis)
{
    int t = threadIdx.x;
    int r = t >> 4, c = t & 15;
    int nb[4]; int cnt = 0;
    if (r > 0)         nb[cnt++] = t - GRIDN;
    if (r < GRIDN - 1) nb[cnt++] = t + GRIDN;
    if (c > 0)         nb[cnt++] = t - 1;
    if (c < GRIDN - 1) nb[cnt++] = t + 1;

    float w[4] = {0.f, 0.f, 0.f, 0.f};
    float deg = 0.f;
    for (int j = 0; j < cnt; j++) { w[j] = sigmoidf_(adjw[t * NN + nb[j]]); deg += w[j]; }
    deg = fmaxf(deg, 1e-6f);
    int over = 0;
    for (int j = 0; j < cnt; j++) { w[j] /= deg; if (w[j] > 0.1f) over++; }
    if (over < 1) w[0] = fmaxf(w[0], 0.5f);
    for (int j = 0; j < 4; j++) {
        g_adjw[t * 4 + j] = (j < cnt) ? w[j] : 0.f;
        g_adjn[t * 4 + j] = (j < cnt) ? nb[j] : t;
    }

    int kr = t >> 6, kc = t & 63;
    float acc = k_b[kc];
    for (int d = 0; d < DD; d++) acc += basis[kr * DD + d] * k_w[kc * DD + d];
    g_K[kr * DD + kc] = acc;
}

// ---------------- fold adjacency into W_in / b_in (tf32-round W) ------------
__global__ void fold_win_kernel(const float* __restrict__ W_in, const float* __restrict__ b_in)
{
    int idx = blockIdx.x * blockDim.x + threadIdx.x;
    if (idx >= HH * (FF / 4)) return;
    int row = idx >> 7, c4 = idx & 127;
    int n = row >> 6, d = row & 63;
    float w0 = g_adjw[n * 4 + 0], w1 = g_adjw[n * 4 + 1];
    float w2 = g_adjw[n * 4 + 2], w3 = g_adjw[n * 4 + 3];
    int   r0 = g_adjn[n * 4 + 0] * DD + d, r1 = g_adjn[n * 4 + 1] * DD + d;
    int   r2 = g_adjn[n * 4 + 2] * DD + d, r3 = g_adjn[n * 4 + 3] * DD + d;
    float4 a = ((const float4*)(W_in + (size_t)r0 * FF))[c4];
    float4 b = ((const float4*)(W_in + (size_t)r1 * FF))[c4];
    float4 c = ((const float4*)(W_in + (size_t)r2 * FF))[c4];
    float4 e = ((const float4*)(W_in + (size_t)r3 * FF))[c4];
    float4 o;
    o.x = wmma::__float_to_tf32(w0 * a.x + w1 * b.x + w2 * c.x + w3 * e.x);
    o.y = wmma::__float_to_tf32(w0 * a.y + w1 * b.y + w2 * c.y + w3 * e.y);
    o.z = wmma::__float_to_tf32(w0 * a.z + w1 * b.z + w2 * c.z + w3 * e.z);
    o.w = wmma::__float_to_tf32(w0 * a.w + w1 * b.w + w2 * c.w + w3 * e.w);
    ((float4*)(g_win2 + (size_t)row * FF))[c4] = o;
    if (c4 == 0)
        g_bin2[row] = w0 * b_in[r0] + w1 * b_in[r1] + w2 * b_in[r2] + w3 * b_in[r3];
}

// ---------------- round x to tf32 --------------------------------------------
__global__ void round_x_kernel(const float* __restrict__ x)
{
    int i = blockIdx.x * blockDim.x + threadIdx.x;
    if (i >= BB * FF / 4) return;
    float4 v = ((const float4*)x)[i];
    v.x = wmma::__float_to_tf32(v.x); v.y = wmma::__float_to_tf32(v.y);
    v.z = wmma::__float_to_tf32(v.z); v.w = wmma::__float_to_tf32(v.w);
    ((float4*)g_xr)[i] = v;
}

// ---------------- Mmat[c, n*4+j] = sum_d basis[j,d] * W_out[c, n*64+d] ------
__global__ void mmat_kernel(const float* __restrict__ W_out, const float* __restrict__ basis)
{
    int gw = (blockIdx.x * blockDim.x + threadIdx.x) >> 5;
    int lane = threadIdx.x & 31;
    if (gw >= CC * NN) return;
    const float* row = W_out + (size_t)gw * DD;
    float v0 = row[lane], v1 = row[lane + 32];
    float r0 = v0 * basis[       lane] + v1 * basis[       lane + 32];
    float r1 = v0 * basis[ 64 +  lane] + v1 * basis[ 64 +  lane + 32];
    float r2 = v0 * basis[128 +  lane] + v1 * basis[128 +  lane + 32];
    float r3 = v0 * basis[192 +  lane] + v1 * basis[192 +  lane + 32];
    #pragma unroll
    for (int o = 16; o; o >>= 1) {
        r0 += __shfl_xor_sync(0xffffffffu, r0, o);
        r1 += __shfl_xor_sync(0xffffffffu, r1, o);
        r2 += __shfl_xor_sync(0xffffffffu, r2, o);
        r3 += __shfl_xor_sync(0xffffffffu, r3, o);
    }
    if (lane == 0)
        ((float4*)g_mmat)[gw] = make_float4(
            wmma::__float_to_tf32(r0), wmma::__float_to_tf32(r1),
            wmma::__float_to_tf32(r2), wmma::__float_to_tf32(r3));
}

// ---------------- GEMM constants (R7-proven shape) ---------------------------
#define BM 128
#define BN 128
#define BK 32
#define GLDS 36
#define GSTAGE 3
#define GSTRIDE ((BM + BN) * GLDS)
#define GEMM_SMEM (GSTAGE * GSTRIDE * 4)           // 110592 B

typedef wmma::fragment<wmma::matrix_a, 16, 16, 8, wmma::precision::tf32, wmma::row_major> AFrag;
typedef wmma::fragment<wmma::matrix_b, 16, 16, 8, wmma::precision::tf32, wmma::col_major> BFrag;
typedef wmma::fragment<wmma::accumulator, 16, 16, 8, float> CFrag;

__device__ __forceinline__ void g_issue(const float* A, const float* B, float* sm,
                                        int t, int m0, int n0, int K, int Nvalid,
                                        int kt, int s)
{
    int k0 = kt * BK;
    float* dstA0 = sm + s * GSTRIDE;
    float* dstB0 = dstA0 + BM * GLDS;
    #pragma unroll
    for (int i = 0; i < 4; i++) {
        int id = t + i * 256;
        int row = id >> 3, c4 = id & 7;
        const float* gA = A + (size_t)(m0 + row) * K + k0 + c4 * 4;
        unsigned int da = (unsigned int)__cvta_generic_to_shared(dstA0 + row * GLDS + c4 * 4);
        asm volatile("cp.async.cg.shared.global [%0], [%1], 16;\n" :: "r"(da), "l"(gA));
        int brow = n0 + row;
        const float* gB = B + (size_t)brow * K + k0 + c4 * 4;
        unsigned int db = (unsigned int)__cvta_generic_to_shared(dstB0 + row * GLDS + c4 * 4);
        int sz = (brow < Nvalid) ? 16 : 0;
        asm volatile("cp.async.cg.shared.global [%0], [%1], 16, %2;\n" :: "r"(db), "l"(gB), "r"(sz));
    }
    asm volatile("cp.async.commit_group;\n" ::: "memory");
}

// ---------------- GEMM1: agg+bias -> fp16 g_nodes_h --------------------------
__global__ __launch_bounds__(256, 2) void gemm1_kernel(
    const float* __restrict__ A, const float* __restrict__ B)
{
    extern __shared__ float sm[];
    int t = threadIdx.x;
    int m0 = blockIdx.y * BM, n0 = blockIdx.x * BN;
    int w = t >> 5, wm = w & 1, wn = w >> 1;
    const int KT = FF / BK;

    CFrag acc[4][2];
    #pragma unroll
    for (int i = 0; i < 4; i++)
        #pragma unroll
        for (int j = 0; j < 2; j++) wmma::fill_fragment(acc[i][j], 0.0f);

    g_issue(A, B, sm, t, m0, n0, FF, HH, 0, 0);
    g_issue(A, B, sm, t, m0, n0, FF, HH, 1, 1);

    for (int kt = 0; kt < KT; kt++) {
        asm volatile("cp.async.wait_group 1;\n" ::: "memory");
        __syncthreads();
        if (kt + 2 < KT)
            g_issue(A, B, sm, t, m0, n0, FF, HH, kt + 2, (kt + 2) % GSTAGE);

        const float* sa = sm + (kt % GSTAGE) * GSTRIDE;
        const float* sb = sa + BM * GLDS;
        #pragma unroll
        for (int kk = 0; kk < BK / 8; kk++) {
            AFrag af[4]; BFrag bf[2];
            #pragma unroll
            for (int i = 0; i < 4; i++)
                wmma::load_matrix_sync(af[i], sa + (wm * 64 + i * 16) * GLDS + kk * 8, GLDS);
            #pragma unroll
            for (int j = 0; j < 2; j++)
                wmma::load_matrix_sync(bf[j], sb + (wn * 32 + j * 16) * GLDS + kk * 8, GLDS);
            #pragma unroll
            for (int i = 0; i < 4; i++)
                #pragma unroll
                for (int j = 0; j < 2; j++)
                    wmma::mma_sync(acc[i][j], af[i], bf[j], acc[i][j]);
        }
    }

    // epilogue: stage, add bias, convert fp16, coalesced half2 stores
    __syncthreads();
    float* tile  = sm;               // 128 x 132
    float* sbias = sm + 128 * 132;   // 128
    if (t < 128) sbias[t] = g_bin2[n0 + t];
    #pragma unroll
    for (int i = 0; i < 4; i++)
        #pragma unroll
        for (int j = 0; j < 2; j++)
            wmma::store_matrix_sync(tile + (wm * 64 + i * 16) * 132 + wn * 32 + j * 16,
                                    acc[i][j], 132, wmma::mem_row_major);
    __syncthreads();
    for (int idx = t; idx < BM * 64; idx += 256) {
        int r = idx >> 6, c2 = idx & 63;
        int c = c2 * 2;
        float v0 = tile[r * 132 + c]     + sbias[c];
        float v1 = tile[r * 132 + c + 1] + sbias[c + 1];
        *((__half2*)(g_nodes_h + (size_t)(m0 + r) * HH + n0 + c)) = __floats2half2_rn(v0, v1);
    }
}

// ---------------- readout GEMM (fused bias, direct to d_out) -----------------
__global__ __launch_bounds__(256, 2) void gemm_readout(
    const float* __restrict__ A, const float* __restrict__ B, float* __restrict__ C,
    int Nvalid, int K, int ldc, const float* __restrict__ bias)
{
    extern __shared__ float sm[];
    int t = threadIdx.x;
    int m0 = blockIdx.y * BM, n0 = blockIdx.x * BN;
    int w = t >> 5, wm = w & 1, wn = w >> 1;
    int KT = K / BK;

    CFrag acc[4][2];
    #pragma unroll
    for (int i = 0; i < 4; i++)
        #pragma unroll
        for (int j = 0; j < 2; j++) wmma::fill_fragment(acc[i][j], 0.0f);

    g_issue(A, B, sm, t, m0, n0, K, Nvalid, 0, 0);
    g_issue(A, B, sm, t, m0, n0, K, Nvalid, 1, 1);

    for (int kt = 0; kt < KT; kt++) {
        asm volatile("cp.async.wait_group 1;\n" ::: "memory");
        __syncthreads();
        if (kt + 2 < KT)
            g_issue(A, B, sm, t, m0, n0, K, Nvalid, kt + 2, (kt + 2) % GSTAGE);

        const float* sa = sm + (kt % GSTAGE) * GSTRIDE;
        const float* sb = sa + BM * GLDS;
        #pragma unroll
        for (int kk = 0; kk < BK / 8; kk++) {
            AFrag af[4]; BFrag bf[2];
            #pragma unroll
            for (int i = 0; i < 4; i++)
                wmma::load_matrix_sync(af[i], sa + (wm * 64 + i * 16) * GLDS + kk * 8, GLDS);
            #pragma unroll
            for (int j = 0; j < 2; j++)
                wmma::load_matrix_sync(bf[j], sb + (wn * 32 + j * 16) * GLDS + kk * 8, GLDS);
            #pragma unroll
            for (int i = 0; i < 4; i++)
                #pragma unroll
                for (int j = 0; j < 2; j++)
                    wmma::mma_sync(acc[i][j], af[i], bf[j], acc[i][j]);
        }
    }

    __syncthreads();
    float* tile = sm;   // 128 x 132 staging
    #pragma unroll
    for (int i = 0; i < 4; i++)
        #pragma unroll
        for (int j = 0; j < 2; j++)
            wmma::store_matrix_sync(tile + (wm * 64 + i * 16) * 132 + wn * 32 + j * 16,
                                    acc[i][j], 132, wmma::mem_row_major);
    __syncthreads();
    for (int idx = t; idx < BM * BN; idx += 256) {
        int r = idx >> 7, c = idx & 127;
        int col = n0 + c;
        if (col < Nvalid)
            C[(size_t)(m0 + r) * ldc + col] = tile[r * 132 + c] + bias[col];
    }
}

// ---------------- persistent middle (fp16 input, R10-proven phases) ----------
#define MLD 68
#define MID_GRID 148
constexpr int MID_SMEM_FLOATS = 2 * 256 * MLD + 3 * 64 * MLD + 256 + 64 + 64;
constexpr int MID_SMEM_BYTES  = MID_SMEM_FLOATS * 4;   // ~193 KB, 1 CTA/SM, 16 warps

__global__ __launch_bounds__(512) void middle_kernel(
    const float* __restrict__ V_slow, const float* __restrict__ sem_mem,
    const float* __restrict__ mix_w, const float* __restrict__ mix_b,
    const float* __restrict__ q_w, const float* __restrict__ q_b)
{
    extern __shared__ float smem_[];
    float* sA   = smem_;               // 256*68 (y_pred, v_pred, cell_out)
    float* sB   = sA + 256 * MLD;      // 256*68 (agg, v, Q)
    float* sV   = sB + 256 * MLD;      // 64*68
    float* sS   = sV + 64 * MLD;       // 64*68
    float* sQm  = sS + 64 * MLD;       // 64*68
    float* sKb  = sQm + 64 * MLD;      // 256
    float* sqb  = sKb + 256;           // 64
    float* smw  = sqb + 64;            // 64

    int t = threadIdx.x;
    int w = t >> 5;
    int rb = (w >> 1) * 32;            // 8 row-blocks of 32
    int cb = (w & 1) * 32;             // 2 col-blocks of 32
    int n2 = t >> 1, dh = (t & 1) * 32;

    // weights once per CTA
    for (int i = t; i < 64 * 64; i += 512) {
        int r = i >> 6, c2 = i & 63;
        sV[r * MLD + c2]  = wmma::__float_to_tf32(V_slow[i]);
        sS[r * MLD + c2]  = wmma::__float_to_tf32(sem_mem[i]);
        sQm[r * MLD + c2] = wmma::__float_to_tf32(q_w[i]);
    }
    if (t < 256) sKb[t] = g_K[t];
    if (t < 64) { sqb[t] = q_b[t]; smw[t] = mix_w[t]; }
    float mixb = mix_b[0];

    // prefetch first batch (fp16: 16384 halves = 2048 uint4)
    int b = blockIdx.x;
    uint4 pre[4];
    {
        const uint4* np_ = (const uint4*)(g_nodes_h + (size_t)b * HH);
        #pragma unroll
        for (int j = 0; j < 4; j++) pre[j] = np_[t + j * 512];
    }

    while (b < BB) {
        int nb = b + MID_GRID;
        __syncthreads();   // prev iteration fully consumed (incl. weight init on iter 0)

        // agg (bias already folded; fp16 grid == tf32 grid) -> sB
        #pragma unroll
        for (int j = 0; j < 4; j++) {
            int i = t + j * 512;
            int n = i >> 3, d = (i & 7) * 8;
            float* dst = &sB[n * MLD + d];
            const __half2* hp = (const __half2*)&pre[j];
            #pragma unroll
            for (int q = 0; q < 4; q++) {
                float2 f = __half22float2(hp[q]);
                dst[q * 2]     = f.x;
                dst[q * 2 + 1] = f.y;
            }
        }
        __syncthreads();

        // v = clip(agg @ V^T), y_pred = clip(agg @ S^T)
        {
            CFrag vf[2][2], yf[2][2];
            #pragma unroll
            for (int i = 0; i < 2; i++)
                #pragma unroll
                for (int j = 0; j < 2; j++) { wmma::fill_fragment(vf[i][j], 0.f); wmma::fill_fragment(yf[i][j], 0.f); }
            #pragma unroll
            for (int kk = 0; kk < 8; kk++) {
                AFrag a0, a1; BFrag bv0, bv1, bs0, bs1;
                wmma::load_matrix_sync(a0, &sB[(rb     ) * MLD + kk * 8], MLD);
                wmma::load_matrix_sync(a1, &sB[(rb + 16) * MLD + kk * 8], MLD);
                wmma::load_matrix_sync(bv0, &sV[(cb     ) * MLD + kk * 8], MLD);
                wmma::load_matrix_sync(bv1, &sV[(cb + 16) * MLD + kk * 8], MLD);
                wmma::load_matrix_sync(bs0, &sS[(cb     ) * MLD + kk * 8], MLD);
                wmma::load_matrix_sync(bs1, &sS[(cb + 16) * MLD + kk * 8], MLD);
                wmma::mma_sync(vf[0][0], a0, bv0, vf[0][0]);
                wmma::mma_sync(vf[0][1], a0, bv1, vf[0][1]);
                wmma::mma_sync(vf[1][0], a1, bv0, vf[1][0]);
                wmma::mma_sync(vf[1][1], a1, bv1, vf[1][1]);
                wmma::mma_sync(yf[0][0], a0, bs0, yf[0][0]);
                wmma::mma_sync(yf[0][1], a0, bs1, yf[0][1]);
                wmma::mma_sync(yf[1][0], a1, bs0, yf[1][0]);
                wmma::mma_sync(yf[1][1], a1, bs1, yf[1][1]);
            }
            #pragma unroll
            for (int i = 0; i < 2; i++)
                #pragma unroll
                for (int j = 0; j < 2; j++) {
                    #pragma unroll
                    for (int e = 0; e < 8; e++) {
                        vf[i][j].x[e] = clip3(vf[i][j].x[e]);
                        yf[i][j].x[e] = clip3(yf[i][j].x[e]);
                    }
                    wmma::store_matrix_sync(&sA[(rb + i * 16) * MLD + cb + j * 16], yf[i][j], MLD, wmma::mem_row_major);
                }
            __syncthreads();
            #pragma unroll
            for (int i = 0; i < 2; i++)
                #pragma unroll
                for (int j = 0; j < 2; j++)
                    wmma::store_matrix_sync(&sB[(rb + i * 16) * MLD + cb + j * 16], vf[i][j], MLD, wmma::mem_row_major);
        }
        __syncthreads();

        // mix = sigmoid(v . mix_w + mix_b); y_pred -> tf32 in place
        float m;
        {
            float acc2 = 0.f;
            const float* vp = &sB[n2 * MLD + dh];
            #pragma unroll
            for (int d = 0; d < 32; d++) acc2 += vp[d] * smw[dh + d];
            acc2 += __shfl_xor_sync(0xffffffffu, acc2, 1);
            m = sigmoidf_(acc2 + mixb);
            float* ya = &sA[n2 * MLD + dh];
            #pragma unroll
            for (int d = 0; d < 32; d++) ya[d] = wmma::__float_to_tf32(ya[d]);
        }
        __syncthreads();

        // v_pred = clip(y_pred @ V^T) -> sA
        {
            CFrag pf[2][2];
            #pragma unroll
            for (int i = 0; i < 2; i++)
                #pragma unroll
                for (int j = 0; j < 2; j++) wmma::fill_fragment(pf[i][j], 0.f);
            #pragma unroll
            for (int kk = 0; kk < 8; kk++) {
                AFrag a0, a1; BFrag bv0, bv1;
                wmma::load_matrix_sync(a0, &sA[(rb     ) * MLD + kk * 8], MLD);
                wmma::load_matrix_sync(a1, &sA[(rb + 16) * MLD + kk * 8], MLD);
                wmma::load_matrix_sync(bv0, &sV[(cb     ) * MLD + kk * 8], MLD);
                wmma::load_matrix_sync(bv1, &sV[(cb + 16) * MLD + kk * 8], MLD);
                wmma::mma_sync(pf[0][0], a0, bv0, pf[0][0]);
                wmma::mma_sync(pf[0][1], a0, bv1, pf[0][1]);
                wmma::mma_sync(pf[1][0], a1, bv0, pf[1][0]);
                wmma::mma_sync(pf[1][1], a1, bv1, pf[1][1]);
            }
            #pragma unroll
            for (int i = 0; i < 2; i++)
                #pragma unroll
                for (int j = 0; j < 2; j++)
                    #pragma unroll
                    for (int e = 0; e < 8; e++) pf[i][j].x[e] = clip3(pf[i][j].x[e]);
            __syncthreads();
            #pragma unroll
            for (int i = 0; i < 2; i++)
                #pragma unroll
                for (int j = 0; j < 2; j++)
                    wmma::store_matrix_sync(&sA[(rb + i * 16) * MLD + cb + j * 16], pf[i][j], MLD, wmma::mem_row_major);
        }
        __syncthreads();

        // cell_out = tf32(clip(mix*v + (1-mix)*v_pred)) -> sA
        {
            const float* va = &sB[n2 * MLD + dh];
            float* pa = &sA[n2 * MLD + dh];
            #pragma unroll
            for (int d = 0; d < 32; d++)
                pa[d] = wmma::__float_to_tf32(clip3(m * va[d] + (1.f - m) * pa[d]));
        }
        __syncthreads();

        // Q = cell_out @ q_w^T -> sB
        {
            CFrag qf[2][2];
            #pragma unroll
            for (int i = 0; i < 2; i++)
                #pragma unroll
                for (int j = 0; j < 2; j++) wmma::fill_fragment(qf[i][j], 0.f);
            #pragma unroll
            for (int kk = 0; kk < 8; kk++) {
                AFrag a0, a1; BFrag bq0, bq1;
                wmma::load_matrix_sync(a0, &sA[(rb     ) * MLD + kk * 8], MLD);
                wmma::load_matrix_sync(a1, &sA[(rb + 16) * MLD + kk * 8], MLD);
                wmma::load_matrix_sync(bq0, &sQm[(cb     ) * MLD + kk * 8], MLD);
                wmma::load_matrix_sync(bq1, &sQm[(cb + 16) * MLD + kk * 8], MLD);
                wmma::mma_sync(qf[0][0], a0, bq0, qf[0][0]);
                wmma::mma_sync(qf[0][1], a0, bq1, qf[0][1]);
                wmma::mma_sync(qf[1][0], a1, bq0, qf[1][0]);
                wmma::mma_sync(qf[1][1], a1, bq1, qf[1][1]);
            }
            #pragma unroll
            for (int i = 0; i < 2; i++)
                #pragma unroll
                for (int j = 0; j < 2; j++)
                    wmma::store_matrix_sync(&sB[(rb + i * 16) * MLD + cb + j * 16], qf[i][j], MLD, wmma::mem_row_major);
        }
        __syncthreads();

        // prefetch next batch (hidden under attention + loop-top)
        if (nb < BB) {
            const uint4* np_ = (const uint4*)(g_nodes_h + (size_t)nb * HH);
            #pragma unroll
            for (int j = 0; j < 4; j++) pre[j] = np_[t + j * 512];
        }

        // attention: 2 threads/row, 4 dots + 1-step shuffle, softmax -> g_w
        {
            float qv[32];
            #pragma unroll
            for (int d = 0; d < 32; d++) qv[d] = sB[n2 * MLD + dh + d] + sqb[dh + d];
            float s0 = 0.f, s1 = 0.f, s2 = 0.f, s3 = 0.f;
            #pragma unroll
            for (int d = 0; d < 32; d++) {
                s0 += qv[d] * sKb[dh + d];
                s1 += qv[d] * sKb[64 + dh + d];
                s2 += qv[d] * sKb[128 + dh + d];
                s3 += qv[d] * sKb[192 + dh + d];
            }
            s0 += __shfl_xor_sync(0xffffffffu, s0, 1);
            s1 += __shfl_xor_sync(0xffffffffu, s1, 1);
            s2 += __shfl_xor_sync(0xffffffffu, s2, 1);
            s3 += __shfl_xor_sync(0xffffffffu, s3, 1);
            if ((t & 1) == 0) {
                s0 *= 0.125f; s1 *= 0.125f; s2 *= 0.125f; s3 *= 0.125f;
                float mx = fmaxf(fmaxf(s0, s1), fmaxf(s2, s3));
                float e0 = expf(s0 - mx), e1 = expf(s1 - mx), e2 = expf(s2 - mx), e3 = expf(s3 - mx);
                float inv = 1.f / (e0 + e1 + e2 + e3);
                ((float4*)(g_w + (size_t)b * CPAD))[n2] = make_float4(
                    wmma::__float_to_tf32(e0 * inv), wmma::__float_to_tf32(e1 * inv),
                    wmma::__float_to_tf32(e2 * inv), wmma::__float_to_tf32(e3 * inv));
            }
        }

        b = nb;
    }
}

// ---------------- launcher ---------------------------------------------------
extern "C" void kernel_launch(void* const* d_in, const int* in_sizes, int n_in,
                              void* d_out, int out_size)
{
    (void)in_sizes; (void)n_in; (void)out_size;
    const float* x      = (const float*)d_in[0];
    const float* W_in   = (const float*)d_in[1];
    const float* b_in   = (const float*)d_in[2];
    const float* adj_w  = (const float*)d_in[3];
    const float* V_slow = (const float*)d_in[5];
    const float* sem    = (const float*)d_in[6];
    const float* mix_w  = (const float*)d_in[7];
    const float* mix_b  = (const float*)d_in[8];
    const float* basis  = (const float*)d_in[9];
    const float* q_w    = (const float*)d_in[10];
    const float* q_b    = (const float*)d_in[11];
    const float* k_w    = (const float*)d_in[12];
    const float* k_b    = (const float*)d_in[13];
    const float* W_out  = (const float*)d_in[14];
    const float* b_out  = (const float*)d_in[15];
    float* out = (float*)d_out;

    cudaFuncSetAttribute(gemm1_kernel, cudaFuncAttributeMaxDynamicSharedMemorySize, GEMM_SMEM);
    cudaFuncSetAttribute(gemm_readout, cudaFuncAttributeMaxDynamicSharedMemorySize, GEMM_SMEM);
    cudaFuncSetAttribute(middle_kernel, cudaFuncAttributeMaxDynamicSharedMemorySize, MID_SMEM_BYTES);

    void *p_w = 0, *p_mmat = 0, *p_win2 = 0, *p_xr = 0;
    cudaGetSymbolAddress(&p_w,     g_w);
    cudaGetSymbolAddress(&p_mmat,  g_mmat);
    cudaGetSymbolAddress(&p_win2,  g_win2);
    cudaGetSymbolAddress(&p_xr,    g_xr);

    prep_kernel<<<1, 256>>>(adj_w, k_w, k_b, basis);
    fold_win_kernel<<<(HH * (FF / 4) + 255) / 256, 256>>>(W_in, b_in);
    round_x_kernel<<<(BB * FF / 4 + 255) / 256, 256>>>(x);
    mmat_kernel<<<(CC * NN) / 8, 256>>>(W_out, basis);

    // agg+bias = xr @ W_in'^T (+ b_in'), stored fp16
    gemm1_kernel<<<dim3(HH / BN, BB / BM), 256, GEMM_SMEM>>>(
        (const float*)p_xr, (const float*)p_win2);

    // persistent middle
    middle_kernel<<<MID_GRID, 512, MID_SMEM_BYTES>>>(V_slow, sem, mix_w, mix_b, q_w, q_b);

    // logits = w @ Mmat^T + b_out  (direct store to d_out)
    gemm_readout<<<dim3(CPAD / BN, BB / BM), 256, GEMM_SMEM>>>(
        (const float*)p_w, (const float*)p_mmat, out, CC, CPAD, CC, b_out);
}

// round 12
// speedup vs baseline: 2.5811x; 2.5811x over previous
#include <cuda_runtime.h>
#include <mma.h>
#include <math.h>
#include <stdint.h>
#include <cuda_fp16.h>

using namespace nvcuda;

#define GRIDN 16
#define NN 256
#define DD 64
#define BB 4096
#define FF 512
#define HH 16384
#define CC 1000
#define CPAD 1024

// ---------------- scratch ----------------------------------------------------
__device__ float  g_nodes[(size_t)BB * HH];     // agg (fp32, no bias)
__device__ __half g_xh[(size_t)BB * FF];        // x rounded to fp16
__device__ __half g_win2h[(size_t)HH * FF];     // adj-folded W_in (fp16)
__device__ float  g_bin2[HH];                   // folded b_in (fp32)
__device__ __half g_wh[(size_t)BB * CPAD];      // softmax weights (fp16)
__device__ __half g_mmath[(size_t)CC * CPAD];   // folded basis x W_out (fp16)
__device__ float  g_adjw[NN * 4];
__device__ int    g_adjn[NN * 4];
__device__ float  g_K[4 * DD];

__device__ __forceinline__ float sigmoidf_(float x) { return 1.0f / (1.0f + expf(-x)); }
__device__ __forceinline__ float clip3(float x) { return fminf(fmaxf(x, -3.0f), 3.0f); }

// ---------------- prep: adjacency rows + K = basis @ k_w^T + k_b ------------
__global__ void prep_kernel(const float* __restrict__ adjw,
                            const float* __restrict__ k_w,
                            const float* __restrict__ k_b,
                            const float* __restrict__ basis)
{
    int t = threadIdx.x;
    int r = t >> 4, c = t & 15;
    int nb[4]; int cnt = 0;
    if (r > 0)         nb[cnt++] = t - GRIDN;
    if (r < GRIDN - 1) nb[cnt++] = t + GRIDN;
    if (c > 0)         nb[cnt++] = t - 1;
    if (c < GRIDN - 1) nb[cnt++] = t + 1;

    float w[4] = {0.f, 0.f, 0.f, 0.f};
    float deg = 0.f;
    for (int j = 0; j < cnt; j++) { w[j] = sigmoidf_(adjw[t * NN + nb[j]]); deg += w[j]; }
    deg = fmaxf(deg, 1e-6f);
    int over = 0;
    for (int j = 0; j < cnt; j++) { w[j] /= deg; if (w[j] > 0.1f) over++; }
    if (over < 1) w[0] = fmaxf(w[0], 0.5f);
    for (int j = 0; j < 4; j++) {
        g_adjw[t * 4 + j] = (j < cnt) ? w[j] : 0.f;
        g_adjn[t * 4 + j] = (j < cnt) ? nb[j] : t;
    }

    int kr = t >> 6, kc = t & 63;
    float acc = k_b[kc];
    for (int d = 0; d < DD; d++) acc += basis[kr * DD + d] * k_w[kc * DD + d];
    g_K[kr * DD + kc] = acc;
}

// ---------------- fold adjacency into W_in / b_in (fp16-round W) ------------
__global__ void fold_win_kernel(const float* __restrict__ W_in, const float* __restrict__ b_in)
{
    int idx = blockIdx.x * blockDim.x + threadIdx.x;
    if (idx >= HH * (FF / 4)) return;
    int row = idx >> 7, c4 = idx & 127;
    int n = row >> 6, d = row & 63;
    float w0 = g_adjw[n * 4 + 0], w1 = g_adjw[n * 4 + 1];
    float w2 = g_adjw[n * 4 + 2], w3 = g_adjw[n * 4 + 3];
    int   r0 = g_adjn[n * 4 + 0] * DD + d, r1 = g_adjn[n * 4 + 1] * DD + d;
    int   r2 = g_adjn[n * 4 + 2] * DD + d, r3 = g_adjn[n * 4 + 3] * DD + d;
    float4 a = ((const float4*)(W_in + (size_t)r0 * FF))[c4];
    float4 b = ((const float4*)(W_in + (size_t)r1 * FF))[c4];
    float4 c = ((const float4*)(W_in + (size_t)r2 * FF))[c4];
    float4 e = ((const float4*)(W_in + (size_t)r3 * FF))[c4];
    __half2 h0 = __floats2half2_rn(w0 * a.x + w1 * b.x + w2 * c.x + w3 * e.x,
                                   w0 * a.y + w1 * b.y + w2 * c.y + w3 * e.y);
    __half2 h1 = __floats2half2_rn(w0 * a.z + w1 * b.z + w2 * c.z + w3 * e.z,
                                   w0 * a.w + w1 * b.w + w2 * c.w + w3 * e.w);
    __half2* dst = (__half2*)(g_win2h + (size_t)row * FF + c4 * 4);
    dst[0] = h0; dst[1] = h1;
    if (c4 == 0)
        g_bin2[row] = w0 * b_in[r0] + w1 * b_in[r1] + w2 * b_in[r2] + w3 * b_in[r3];
}

// ---------------- round x to fp16 --------------------------------------------
__global__ void round_x_kernel(const float* __restrict__ x)
{
    int i = blockIdx.x * blockDim.x + threadIdx.x;
    if (i >= BB * FF / 4) return;
    float4 v = ((const float4*)x)[i];
    __half2* dst = (__half2*)(g_xh + (size_t)i * 4);
    dst[0] = __floats2half2_rn(v.x, v.y);
    dst[1] = __floats2half2_rn(v.z, v.w);
}

// ---------------- Mmat[c, n*4+j] = sum_d basis[j,d] * W_out[c, n*64+d] ------
__global__ void mmat_kernel(const float* __restrict__ W_out, const float* __restrict__ basis)
{
    int gw = (blockIdx.x * blockDim.x + threadIdx.x) >> 5;
    int lane = threadIdx.x & 31;
    if (gw >= CC * NN) return;
    const float* row = W_out + (size_t)gw * DD;
    float v0 = row[lane], v1 = row[lane + 32];
    float r0 = v0 * basis[       lane] + v1 * basis[       lane + 32];
    float r1 = v0 * basis[ 64 +  lane] + v1 * basis[ 64 +  lane + 32];
    float r2 = v0 * basis[128 +  lane] + v1 * basis[128 +  lane + 32];
    float r3 = v0 * basis[192 +  lane] + v1 * basis[192 +  lane + 32];
    #pragma unroll
    for (int o = 16; o; o >>= 1) {
        r0 += __shfl_xor_sync(0xffffffffu, r0, o);
        r1 += __shfl_xor_sync(0xffffffffu, r1, o);
        r2 += __shfl_xor_sync(0xffffffffu, r2, o);
        r3 += __shfl_xor_sync(0xffffffffu, r3, o);
    }
    if (lane == 0) {
        __half2* dst = (__half2*)(g_mmath + (size_t)gw * 4);
        dst[0] = __floats2half2_rn(r0, r1);
        dst[1] = __floats2half2_rn(r2, r3);
    }
}

// ---------------- fp16 GEMM skeleton (128x128, 256 thr, 3-stage) ------------
#define BM 128
#define BN 128
#define HBK 64
#define HLDS 72
#define HSTRIDE ((BM + BN) * HLDS)                  // halves per stage (18432)
#define GEMM_SMEM_H (3 * HSTRIDE * 2)               // 110592 B

typedef wmma::fragment<wmma::matrix_a, 16, 16, 16, __half, wmma::row_major> AFH;
typedef wmma::fragment<wmma::matrix_b, 16, 16, 16, __half, wmma::col_major> BFH;
typedef wmma::fragment<wmma::accumulator, 16, 16, 16, float> CFH;

__device__ __forceinline__ void h_issue(const __half* A, const __half* B, __half* smh,
                                        int t, int m0, int n0, int K, int Nvalid,
                                        int kt, int s)
{
    int k0 = kt * HBK;
    __half* dstA0 = smh + s * HSTRIDE;
    __half* dstB0 = dstA0 + BM * HLDS;
    #pragma unroll
    for (int i = 0; i < 4; i++) {
        int id = t + i * 256;                 // 0..1023
        int row = id >> 3, c8 = id & 7;       // 8 chunks of 8 halves per row
        const __half* gA = A + (size_t)(m0 + row) * K + k0 + c8 * 8;
        unsigned int da = (unsigned int)__cvta_generic_to_shared(dstA0 + row * HLDS + c8 * 8);
        asm volatile("cp.async.cg.shared.global [%0], [%1], 16;\n" :: "r"(da), "l"(gA));
        int brow = n0 + row;
        const __half* gB = B + (size_t)brow * K + k0 + c8 * 8;
        unsigned int db = (unsigned int)__cvta_generic_to_shared(dstB0 + row * HLDS + c8 * 8);
        int sz = (brow < Nvalid) ? 16 : 0;
        asm volatile("cp.async.cg.shared.global [%0], [%1], 16, %2;\n" :: "r"(db), "l"(gB), "r"(sz));
    }
    asm volatile("cp.async.commit_group;\n" ::: "memory");
}

template<bool STORE_OUT>
__global__ __launch_bounds__(256, 2) void gemm_h(
    const __half* __restrict__ A, const __half* __restrict__ B, float* __restrict__ C,
    int Nvalid, int K, int ldc, const float* __restrict__ bias)
{
    extern __shared__ __half smh[];
    float* smf = (float*)smh;
    int t = threadIdx.x;
    int m0 = blockIdx.y * BM, n0 = blockIdx.x * BN;
    int w = t >> 5, wm = w & 1, wn = w >> 1;
    int KT = K / HBK;

    CFH acc[4][2];
    #pragma unroll
    for (int i = 0; i < 4; i++)
        #pragma unroll
        for (int j = 0; j < 2; j++) wmma::fill_fragment(acc[i][j], 0.0f);

    h_issue(A, B, smh, t, m0, n0, K, Nvalid, 0, 0);
    h_issue(A, B, smh, t, m0, n0, K, Nvalid, 1, 1);

    for (int kt = 0; kt < KT; kt++) {
        if (kt == KT - 1) asm volatile("cp.async.wait_group 0;\n" ::: "memory");
        else              asm volatile("cp.async.wait_group 1;\n" ::: "memory");
        __syncthreads();
        if (kt + 2 < KT)
            h_issue(A, B, smh, t, m0, n0, K, Nvalid, kt + 2, (kt + 2) % 3);

        const __half* sa = smh + (kt % 3) * HSTRIDE;
        const __half* sb = sa + BM * HLDS;
        #pragma unroll
        for (int kk = 0; kk < HBK / 16; kk++) {
            AFH af[4]; BFH bf[2];
            #pragma unroll
            for (int i = 0; i < 4; i++)
                wmma::load_matrix_sync(af[i], sa + (wm * 64 + i * 16) * HLDS + kk * 16, HLDS);
            #pragma unroll
            for (int j = 0; j < 2; j++)
                wmma::load_matrix_sync(bf[j], sb + (wn * 32 + j * 16) * HLDS + kk * 16, HLDS);
            #pragma unroll
            for (int i = 0; i < 4; i++)
                #pragma unroll
                for (int j = 0; j < 2; j++)
                    wmma::mma_sync(acc[i][j], af[i], bf[j], acc[i][j]);
        }
    }

    if (STORE_OUT) {
        __syncthreads();
        float* tile = smf;   // 128 x 132 staging
        #pragma unroll
        for (int i = 0; i < 4; i++)
            #pragma unroll
            for (int j = 0; j < 2; j++)
                wmma::store_matrix_sync(tile + (wm * 64 + i * 16) * 132 + wn * 32 + j * 16,
                                        acc[i][j], 132, wmma::mem_row_major);
        __syncthreads();
        for (int idx = t; idx < BM * BN; idx += 256) {
            int r = idx >> 7, c = idx & 127;
            int col = n0 + c;
            if (col < Nvalid)
                C[(size_t)(m0 + r) * ldc + col] = tile[r * 132 + c] + bias[col];
        }
    } else {
        #pragma unroll
        for (int i = 0; i < 4; i++)
            #pragma unroll
            for (int j = 0; j < 2; j++)
                wmma::store_matrix_sync(C + (size_t)(m0 + wm * 64 + i * 16) * ldc + n0 + wn * 32 + j * 16,
                                        acc[i][j], ldc, wmma::mem_row_major);
    }
}

// ---------------- persistent middle (fp16 matmuls, R10 structure) ------------
#define MID_GRID 148
// floats: fA 256*68, fB 256*68, sKb 256, sqb 64, smw 64  -> 35200 floats
// halves: hA 256*72, hV/hS/hQ 64*72 each                 -> 32256 halves
constexpr int MID_SMEM_BYTES = (2 * 256 * 68 + 256 + 64 + 64) * 4 + (256 * 72 + 3 * 64 * 72) * 2; // 205312 B

__global__ __launch_bounds__(512) void middle_kernel(
    const float* __restrict__ V_slow, const float* __restrict__ sem_mem,
    const float* __restrict__ mix_w, const float* __restrict__ mix_b,
    const float* __restrict__ q_w, const float* __restrict__ q_b)
{
    extern __shared__ float smem_[];
    float* fA  = smem_;                 // y_pred -> v_pred
    float* fB  = fA + 256 * 68;         // v -> Q
    float* sKb = fB + 256 * 68;         // 256
    float* sqb = sKb + 256;             // 64
    float* smw = sqb + 64;              // 64
    __half* hA = (__half*)(smw + 64);   // agg -> y(h) -> cell(h)   256*72
    __half* hV = hA + 256 * 72;
    __half* hS = hV + 64 * 72;
    __half* hQ = hS + 64 * 72;

    int t = threadIdx.x;
    int w = t >> 5;
    int rb = (w >> 1) * 32;            // 8 row-blocks of 32
    int cb = (w & 1) * 32;             // 2 col-blocks of 32
    int n2 = t >> 1, dh = (t & 1) * 32;

    // weights once per CTA (fp16)
    for (int i = t; i < 64 * 64; i += 512) {
        int r = i >> 6, c2 = i & 63;
        hV[r * 72 + c2] = __float2half_rn(V_slow[i]);
        hS[r * 72 + c2] = __float2half_rn(sem_mem[i]);
        hQ[r * 72 + c2] = __float2half_rn(q_w[i]);
    }
    if (t < 256) sKb[t] = g_K[t];
    if (t < 64) { sqb[t] = q_b[t]; smw[t] = mix_w[t]; }
    float mixb = mix_b[0];

    const float4* bp_ = (const float4*)g_bin2;

    // prefetch first batch
    int b = blockIdx.x;
    float4 pre[8];
    {
        const float4* np_ = (const float4*)(g_nodes + (size_t)b * HH);
        #pragma unroll
        for (int j = 0; j < 8; j++) pre[j] = np_[t + j * 512];
    }

    while (b < BB) {
        int nb = b + MID_GRID;
        __syncthreads();   // prev iteration fully consumed

        // agg + bias -> hA (fp16; same 11-bit grid as tf32)
        #pragma unroll
        for (int j = 0; j < 8; j++) {
            int i = t + j * 512;
            float4 v = pre[j], bbv = bp_[i];
            int n = i >> 4, d = (i & 15) << 2;
            __half2* dst = (__half2*)&hA[n * 72 + d];
            dst[0] = __floats2half2_rn(v.x + bbv.x, v.y + bbv.y);
            dst[1] = __floats2half2_rn(v.z + bbv.z, v.w + bbv.w);
        }
        __syncthreads();

        // v = clip(agg @ V^T) -> fB, y = clip(agg @ S^T) -> fA
        {
            CFH vf[2][2], yf[2][2];
            #pragma unroll
            for (int i = 0; i < 2; i++)
                #pragma unroll
                for (int j = 0; j < 2; j++) { wmma::fill_fragment(vf[i][j], 0.f); wmma::fill_fragment(yf[i][j], 0.f); }
            #pragma unroll
            for (int kk = 0; kk < 4; kk++) {
                AFH a0, a1; BFH bv0, bv1, bs0, bs1;
                wmma::load_matrix_sync(a0, &hA[(rb     ) * 72 + kk * 16], 72);
                wmma::load_matrix_sync(a1, &hA[(rb + 16) * 72 + kk * 16], 72);
                wmma::load_matrix_sync(bv0, &hV[(cb     ) * 72 + kk * 16], 72);
                wmma::load_matrix_sync(bv1, &hV[(cb + 16) * 72 + kk * 16], 72);
                wmma::load_matrix_sync(bs0, &hS[(cb     ) * 72 + kk * 16], 72);
                wmma::load_matrix_sync(bs1, &hS[(cb + 16) * 72 + kk * 16], 72);
                wmma::mma_sync(vf[0][0], a0, bv0, vf[0][0]);
                wmma::mma_sync(vf[0][1], a0, bv1, vf[0][1]);
                wmma::mma_sync(vf[1][0], a1, bv0, vf[1][0]);
                wmma::mma_sync(vf[1][1], a1, bv1, vf[1][1]);
                wmma::mma_sync(yf[0][0], a0, bs0, yf[0][0]);
                wmma::mma_sync(yf[0][1], a0, bs1, yf[0][1]);
                wmma::mma_sync(yf[1][0], a1, bs0, yf[1][0]);
                wmma::mma_sync(yf[1][1], a1, bs1, yf[1][1]);
            }
            #pragma unroll
            for (int i = 0; i < 2; i++)
                #pragma unroll
                for (int j = 0; j < 2; j++) {
                    #pragma unroll
                    for (int e = 0; e < 8; e++) {
                        vf[i][j].x[e] = clip3(vf[i][j].x[e]);
                        yf[i][j].x[e] = clip3(yf[i][j].x[e]);
                    }
                    wmma::store_matrix_sync(&fA[(rb + i * 16) * 68 + cb + j * 16], yf[i][j], 68, wmma::mem_row_major);
                    wmma::store_matrix_sync(&fB[(rb + i * 16) * 68 + cb + j * 16], vf[i][j], 68, wmma::mem_row_major);
                }
        }
        __syncthreads();

        // mix = sigmoid(v . mix_w + mix_b); y: fA -> hA (fp16)
        float m;
        {
            float acc2 = 0.f;
            const float* vp = &fB[n2 * 68 + dh];
            #pragma unroll
            for (int d = 0; d < 32; d++) acc2 += vp[d] * smw[dh + d];
            acc2 += __shfl_xor_sync(0xffffffffu, acc2, 1);
            m = sigmoidf_(acc2 + mixb);
            const float* ya = &fA[n2 * 68 + dh];
            __half2* dst = (__half2*)&hA[n2 * 72 + dh];
            #pragma unroll
            for (int d = 0; d < 16; d++)
                dst[d] = __floats2half2_rn(ya[d * 2], ya[d * 2 + 1]);
        }
        __syncthreads();

        // v_pred = clip(y(h) @ V^T) -> fA
        {
            CFH pf[2][2];
            #pragma unroll
            for (int i = 0; i < 2; i++)
                #pragma unroll
                for (int j = 0; j < 2; j++) wmma::fill_fragment(pf[i][j], 0.f);
            #pragma unroll
            for (int kk = 0; kk < 4; kk++) {
                AFH a0, a1; BFH bv0, bv1;
                wmma::load_matrix_sync(a0, &hA[(rb     ) * 72 + kk * 16], 72);
                wmma::load_matrix_sync(a1, &hA[(rb + 16) * 72 + kk * 16], 72);
                wmma::load_matrix_sync(bv0, &hV[(cb     ) * 72 + kk * 16], 72);
                wmma::load_matrix_sync(bv1, &hV[(cb + 16) * 72 + kk * 16], 72);
                wmma::mma_sync(pf[0][0], a0, bv0, pf[0][0]);
                wmma::mma_sync(pf[0][1], a0, bv1, pf[0][1]);
                wmma::mma_sync(pf[1][0], a1, bv0, pf[1][0]);
                wmma::mma_sync(pf[1][1], a1, bv1, pf[1][1]);
            }
            #pragma unroll
            for (int i = 0; i < 2; i++)
                #pragma unroll
                for (int j = 0; j < 2; j++) {
                    #pragma unroll
                    for (int e = 0; e < 8; e++) pf[i][j].x[e] = clip3(pf[i][j].x[e]);
                    wmma::store_matrix_sync(&fA[(rb + i * 16) * 68 + cb + j * 16], pf[i][j], 68, wmma::mem_row_major);
                }
        }
        __syncthreads();

        // cell = fp16(clip(m*v + (1-m)*v_pred)) -> hA
        {
            const float* va = &fB[n2 * 68 + dh];
            const float* pa = &fA[n2 * 68 + dh];
            __half2* dst = (__half2*)&hA[n2 * 72 + dh];
            #pragma unroll
            for (int d = 0; d < 16; d++) {
                float c0 = clip3(m * va[d * 2]     + (1.f - m) * pa[d * 2]);
                float c1 = clip3(m * va[d * 2 + 1] + (1.f - m) * pa[d * 2 + 1]);
                dst[d] = __floats2half2_rn(c0, c1);
            }
        }
        __syncthreads();

        // Q = cell(h) @ q_w^T -> fB
        {
            CFH qf[2][2];
            #pragma unroll
            for (int i = 0; i < 2; i++)
                #pragma unroll
                for (int j = 0; j < 2; j++) wmma::fill_fragment(qf[i][j], 0.f);
            #pragma unroll
            for (int kk = 0; kk < 4; kk++) {
                AFH a0, a1; BFH bq0, bq1;
                wmma::load_matrix_sync(a0, &hA[(rb     ) * 72 + kk * 16], 72);
                wmma::load_matrix_sync(a1, &hA[(rb + 16) * 72 + kk * 16], 72);
                wmma::load_matrix_sync(bq0, &hQ[(cb     ) * 72 + kk * 16], 72);
                wmma::load_matrix_sync(bq1, &hQ[(cb + 16) * 72 + kk * 16], 72);
                wmma::mma_sync(qf[0][0], a0, bq0, qf[0][0]);
                wmma::mma_sync(qf[0][1], a0, bq1, qf[0][1]);
                wmma::mma_sync(qf[1][0], a1, bq0, qf[1][0]);
                wmma::mma_sync(qf[1][1], a1, bq1, qf[1][1]);
            }
            #pragma unroll
            for (int i = 0; i < 2; i++)
                #pragma unroll
                for (int j = 0; j < 2; j++)
                    wmma::store_matrix_sync(&fB[(rb + i * 16) * 68 + cb + j * 16], qf[i][j], 68, wmma::mem_row_major);
        }
        __syncthreads();

        // prefetch next batch (hidden under attention + loop-top)
        if (nb < BB) {
            const float4* np_ = (const float4*)(g_nodes + (size_t)nb * HH);
            #pragma unroll
            for (int j = 0; j < 8; j++) pre[j] = np_[t + j * 512];
        }

        // attention: softmax -> g_wh (fp16)
        {
            float qv[32];
            #pragma unroll
            for (int d = 0; d < 32; d++) qv[d] = fB[n2 * 68 + dh + d] + sqb[dh + d];
            float s0 = 0.f, s1 = 0.f, s2 = 0.f, s3 = 0.f;
            #pragma unroll
            for (int d = 0; d < 32; d++) {
                s0 += qv[d] * sKb[dh + d];
                s1 += qv[d] * sKb[64 + dh + d];
                s2 += qv[d] * sKb[128 + dh + d];
                s3 += qv[d] * sKb[192 + dh + d];
            }
            s0 += __shfl_xor_sync(0xffffffffu, s0, 1);
            s1 += __shfl_xor_sync(0xffffffffu, s1, 1);
            s2 += __shfl_xor_sync(0xffffffffu, s2, 1);
            s3 += __shfl_xor_sync(0xffffffffu, s3, 1);
            if ((t & 1) == 0) {
                s0 *= 0.125f; s1 *= 0.125f; s2 *= 0.125f; s3 *= 0.125f;
                float mx = fmaxf(fmaxf(s0, s1), fmaxf(s2, s3));
                float e0 = expf(s0 - mx), e1 = expf(s1 - mx), e2 = expf(s2 - mx), e3 = expf(s3 - mx);
                float inv = 1.f / (e0 + e1 + e2 + e3);
                __half2* dst = (__half2*)(g_wh + (size_t)b * CPAD + n2 * 4);
                dst[0] = __floats2half2_rn(e0 * inv, e1 * inv);
                dst[1] = __floats2half2_rn(e2 * inv, e3 * inv);
            }
        }

        b = nb;
    }
}

// ---------------- launcher ---------------------------------------------------
extern "C" void kernel_launch(void* const* d_in, const int* in_sizes, int n_in,
                              void* d_out, int out_size)
{
    (void)in_sizes; (void)n_in; (void)out_size;
    const float* x      = (const float*)d_in[0];
    const float* W_in   = (const float*)d_in[1];
    const float* b_in   = (const float*)d_in[2];
    const float* adj_w  = (const float*)d_in[3];
    const float* V_slow = (const float*)d_in[5];
    const float* sem    = (const float*)d_in[6];
    const float* mix_w  = (const float*)d_in[7];
    const float* mix_b  = (const float*)d_in[8];
    const float* basis  = (const float*)d_in[9];
    const float* q_w    = (const float*)d_in[10];
    const float* q_b    = (const float*)d_in[11];
    const float* k_w    = (const float*)d_in[12];
    const float* k_b    = (const float*)d_in[13];
    const float* W_out  = (const float*)d_in[14];
    const float* b_out  = (const float*)d_in[15];
    float* out = (float*)d_out;

    cudaFuncSetAttribute(gemm_h<false>, cudaFuncAttributeMaxDynamicSharedMemorySize, GEMM_SMEM_H);
    cudaFuncSetAttribute(gemm_h<true>,  cudaFuncAttributeMaxDynamicSharedMemorySize, GEMM_SMEM_H);
    cudaFuncSetAttribute(middle_kernel, cudaFuncAttributeMaxDynamicSharedMemorySize, MID_SMEM_BYTES);

    void *p_nodes = 0, *p_wh = 0, *p_mmath = 0, *p_win2h = 0, *p_xh = 0;
    cudaGetSymbolAddress(&p_nodes,  g_nodes);
    cudaGetSymbolAddress(&p_wh,     g_wh);
    cudaGetSymbolAddress(&p_mmath,  g_mmath);
    cudaGetSymbolAddress(&p_win2h,  g_win2h);
    cudaGetSymbolAddress(&p_xh,     g_xh);

    prep_kernel<<<1, 256>>>(adj_w, k_w, k_b, basis);
    fold_win_kernel<<<(HH * (FF / 4) + 255) / 256, 256>>>(W_in, b_in);
    round_x_kernel<<<(BB * FF / 4 + 255) / 256, 256>>>(x);
    mmat_kernel<<<(CC * NN) / 8, 256>>>(W_out, basis);

    // agg = xh @ W_in'^T  (fp16 MMA, fp32 accum, direct fp32 store)
    gemm_h<false><<<dim3(HH / BN, BB / BM), 256, GEMM_SMEM_H>>>(
        (const __half*)p_xh, (const __half*)p_win2h, (float*)p_nodes, HH, FF, HH, nullptr);

    // persistent middle (fp16 matmuls)
    middle_kernel<<<MID_GRID, 512, MID_SMEM_BYTES>>>(V_slow, sem, mix_w, mix_b, q_w, q_b);

    // logits = wh @ Mmat^T + b_out  (fp16 MMA, direct store to d_out)
    gemm_h<true><<<dim3(CPAD / BN, BB / BM), 256, GEMM_SMEM_H>>>(
        (const __half*)p_wh, (const __half*)p_mmath, out, CC, CPAD, CC, b_out);
}

// round 13
// speedup vs baseline: 2.7539x; 1.0669x over previous
#include <cuda_runtime.h>
#include <mma.h>
#include <math.h>
#include <stdint.h>
#include <cuda_fp16.h>

using namespace nvcuda;

#define GRIDN 16
#define NN 256
#define DD 64
#define BB 4096
#define FF 512
#define HH 16384
#define CC 1000
#define CPAD 1024

// ---------------- scratch ----------------------------------------------------
__device__ __half g_nodes_h[(size_t)BB * HH];   // agg (fp16, no bias) 128 MB
__device__ __half g_xh[(size_t)BB * FF];        // x rounded to fp16
__device__ __half g_win2h[(size_t)HH * FF];     // adj-folded W_in (fp16)
__device__ float  g_bin2[HH];                   // folded b_in (fp32)
__device__ __half g_wh[(size_t)BB * CPAD];      // softmax weights (fp16)
__device__ __half g_mmath[(size_t)CC * CPAD];   // folded basis x W_out (fp16)
__device__ float  g_adjw[NN * 4];
__device__ int    g_adjn[NN * 4];
__device__ float  g_K[4 * DD];

__device__ __forceinline__ float sigmoidf_(float x) { return 1.0f / (1.0f + expf(-x)); }
__device__ __forceinline__ float clip3(float x) { return fminf(fmaxf(x, -3.0f), 3.0f); }

// ---------------- prep: adjacency rows + K = basis @ k_w^T + k_b ------------
__global__ void prep_kernel(const float* __restrict__ adjw,
                            const float* __restrict__ k_w,
                            const float* __restrict__ k_b,
                            const float* __restrict__ basis)
{
    int t = threadIdx.x;
    int r = t >> 4, c = t & 15;
    int nb[4]; int cnt = 0;
    if (r > 0)         nb[cnt++] = t - GRIDN;
    if (r < GRIDN - 1) nb[cnt++] = t + GRIDN;
    if (c > 0)         nb[cnt++] = t - 1;
    if (c < GRIDN - 1) nb[cnt++] = t + 1;

    float w[4] = {0.f, 0.f, 0.f, 0.f};
    float deg = 0.f;
    for (int j = 0; j < cnt; j++) { w[j] = sigmoidf_(adjw[t * NN + nb[j]]); deg += w[j]; }
    deg = fmaxf(deg, 1e-6f);
    int over = 0;
    for (int j = 0; j < cnt; j++) { w[j] /= deg; if (w[j] > 0.1f) over++; }
    if (over < 1) w[0] = fmaxf(w[0], 0.5f);
    for (int j = 0; j < 4; j++) {
        g_adjw[t * 4 + j] = (j < cnt) ? w[j] : 0.f;
        g_adjn[t * 4 + j] = (j < cnt) ? nb[j] : t;
    }

    int kr = t >> 6, kc = t & 63;
    float acc = k_b[kc];
    for (int d = 0; d < DD; d++) acc += basis[kr * DD + d] * k_w[kc * DD + d];
    g_K[kr * DD + kc] = acc;
}

// ---------------- fold adjacency into W_in / b_in (fp16-round W) ------------
__global__ void fold_win_kernel(const float* __restrict__ W_in, const float* __restrict__ b_in)
{
    int idx = blockIdx.x * blockDim.x + threadIdx.x;
    if (idx >= HH * (FF / 4)) return;
    int row = idx >> 7, c4 = idx & 127;
    int n = row >> 6, d = row & 63;
    float w0 = g_adjw[n * 4 + 0], w1 = g_adjw[n * 4 + 1];
    float w2 = g_adjw[n * 4 + 2], w3 = g_adjw[n * 4 + 3];
    int   r0 = g_adjn[n * 4 + 0] * DD + d, r1 = g_adjn[n * 4 + 1] * DD + d;
    int   r2 = g_adjn[n * 4 + 2] * DD + d, r3 = g_adjn[n * 4 + 3] * DD + d;
    float4 a = ((const float4*)(W_in + (size_t)r0 * FF))[c4];
    float4 b = ((const float4*)(W_in + (size_t)r1 * FF))[c4];
    float4 c = ((const float4*)(W_in + (size_t)r2 * FF))[c4];
    float4 e = ((const float4*)(W_in + (size_t)r3 * FF))[c4];
    __half2 h0 = __floats2half2_rn(w0 * a.x + w1 * b.x + w2 * c.x + w3 * e.x,
                                   w0 * a.y + w1 * b.y + w2 * c.y + w3 * e.y);
    __half2 h1 = __floats2half2_rn(w0 * a.z + w1 * b.z + w2 * c.z + w3 * e.z,
                                   w0 * a.w + w1 * b.w + w2 * c.w + w3 * e.w);
    __half2* dst = (__half2*)(g_win2h + (size_t)row * FF + c4 * 4);
    dst[0] = h0; dst[1] = h1;
    if (c4 == 0)
        g_bin2[row] = w0 * b_in[r0] + w1 * b_in[r1] + w2 * b_in[r2] + w3 * b_in[r3];
}

// ---------------- round x to fp16 --------------------------------------------
__global__ void round_x_kernel(const float* __restrict__ x)
{
    int i = blockIdx.x * blockDim.x + threadIdx.x;
    if (i >= BB * FF / 4) return;
    float4 v = ((const float4*)x)[i];
    __half2* dst = (__half2*)(g_xh + (size_t)i * 4);
    dst[0] = __floats2half2_rn(v.x, v.y);
    dst[1] = __floats2half2_rn(v.z, v.w);
}

// ---------------- Mmat: 2 rows per warp (2x MLP) -----------------------------
__global__ void mmat_kernel(const float* __restrict__ W_out, const float* __restrict__ basis)
{
    int gw = (blockIdx.x * blockDim.x + threadIdx.x) >> 5;   // warp id
    int lane = threadIdx.x & 31;
    int rowi = gw * 2;
    if (rowi >= CC * NN) return;
    const float* rowA = W_out + (size_t)rowi * DD;
    const float* rowB = rowA + DD;
    float a0 = rowA[lane], a1 = rowA[lane + 32];
    float b0 = rowB[lane], b1 = rowB[lane + 32];
    float ba0 = basis[lane],       ba1 = basis[lane + 32];
    float bb0 = basis[64 + lane],  bb1 = basis[96 + lane];
    float bc0 = basis[128 + lane], bc1 = basis[160 + lane];
    float bd0 = basis[192 + lane], bd1 = basis[224 + lane];
    float ra0 = a0 * ba0 + a1 * ba1, ra1 = a0 * bb0 + a1 * bb1;
    float ra2 = a0 * bc0 + a1 * bc1, ra3 = a0 * bd0 + a1 * bd1;
    float rb0 = b0 * ba0 + b1 * ba1, rb1 = b0 * bb0 + b1 * bb1;
    float rb2 = b0 * bc0 + b1 * bc1, rb3 = b0 * bd0 + b1 * bd1;
    #pragma unroll
    for (int o = 16; o; o >>= 1) {
        ra0 += __shfl_xor_sync(0xffffffffu, ra0, o);
        ra1 += __shfl_xor_sync(0xffffffffu, ra1, o);
        ra2 += __shfl_xor_sync(0xffffffffu, ra2, o);
        ra3 += __shfl_xor_sync(0xffffffffu, ra3, o);
        rb0 += __shfl_xor_sync(0xffffffffu, rb0, o);
        rb1 += __shfl_xor_sync(0xffffffffu, rb1, o);
        rb2 += __shfl_xor_sync(0xffffffffu, rb2, o);
        rb3 += __shfl_xor_sync(0xffffffffu, rb3, o);
    }
    if (lane == 0) {
        __half2* d0 = (__half2*)(g_mmath + (size_t)rowi * 4);
        d0[0] = __floats2half2_rn(ra0, ra1);
        d0[1] = __floats2half2_rn(ra2, ra3);
        d0[2] = __floats2half2_rn(rb0, rb1);
        d0[3] = __floats2half2_rn(rb2, rb3);
    }
}

// ---------------- fp16 GEMM skeleton (128x128, 256 thr, 3-stage) ------------
#define BM 128
#define BN 128
#define HBK 64
#define HLDS 72
#define HSTRIDE ((BM + BN) * HLDS)                  // halves per stage (18432)
#define GEMM_SMEM_H (3 * HSTRIDE * 2)               // 110592 B

typedef wmma::fragment<wmma::matrix_a, 16, 16, 16, __half, wmma::row_major> AFH;
typedef wmma::fragment<wmma::matrix_b, 16, 16, 16, __half, wmma::col_major> BFH;
typedef wmma::fragment<wmma::accumulator, 16, 16, 16, float> CFH;
typedef wmma::fragment<wmma::accumulator, 16, 16, 16, __half> CHH;

__device__ __forceinline__ void h_issue(const __half* A, const __half* B, __half* smh,
                                        int t, int m0, int n0, int K, int Nvalid,
                                        int kt, int s)
{
    int k0 = kt * HBK;
    __half* dstA0 = smh + s * HSTRIDE;
    __half* dstB0 = dstA0 + BM * HLDS;
    #pragma unroll
    for (int i = 0; i < 4; i++) {
        int id = t + i * 256;
        int row = id >> 3, c8 = id & 7;
        const __half* gA = A + (size_t)(m0 + row) * K + k0 + c8 * 8;
        unsigned int da = (unsigned int)__cvta_generic_to_shared(dstA0 + row * HLDS + c8 * 8);
        asm volatile("cp.async.cg.shared.global [%0], [%1], 16;\n" :: "r"(da), "l"(gA));
        int brow = n0 + row;
        const __half* gB = B + (size_t)brow * K + k0 + c8 * 8;
        unsigned int db = (unsigned int)__cvta_generic_to_shared(dstB0 + row * HLDS + c8 * 8);
        int sz = (brow < Nvalid) ? 16 : 0;
        asm volatile("cp.async.cg.shared.global [%0], [%1], 16, %2;\n" :: "r"(db), "l"(gB), "r"(sz));
    }
    asm volatile("cp.async.commit_group;\n" ::: "memory");
}

// ---------------- GEMM1: direct fp16 store (no staging) ----------------------
__global__ __launch_bounds__(256, 2) void gemm1_h(
    const __half* __restrict__ A, const __half* __restrict__ B, __half* __restrict__ C)
{
    extern __shared__ __half smh[];
    int t = threadIdx.x;
    int m0 = blockIdx.y * BM, n0 = blockIdx.x * BN;
    int w = t >> 5, wm = w & 1, wn = w >> 1;
    const int KT = FF / HBK;   // 8

    CFH acc[4][2];
    #pragma unroll
    for (int i = 0; i < 4; i++)
        #pragma unroll
        for (int j = 0; j < 2; j++) wmma::fill_fragment(acc[i][j], 0.0f);

    h_issue(A, B, smh, t, m0, n0, FF, HH, 0, 0);
    h_issue(A, B, smh, t, m0, n0, FF, HH, 1, 1);

    for (int kt = 0; kt < KT; kt++) {
        if (kt == KT - 1) asm volatile("cp.async.wait_group 0;\n" ::: "memory");
        else              asm volatile("cp.async.wait_group 1;\n" ::: "memory");
        __syncthreads();
        if (kt + 2 < KT)
            h_issue(A, B, smh, t, m0, n0, FF, HH, kt + 2, (kt + 2) % 3);

        const __half* sa = smh + (kt % 3) * HSTRIDE;
        const __half* sb = sa + BM * HLDS;
        #pragma unroll
        for (int kk = 0; kk < HBK / 16; kk++) {
            AFH af[4]; BFH bf[2];
            #pragma unroll
            for (int i = 0; i < 4; i++)
                wmma::load_matrix_sync(af[i], sa + (wm * 64 + i * 16) * HLDS + kk * 16, HLDS);
            #pragma unroll
            for (int j = 0; j < 2; j++)
                wmma::load_matrix_sync(bf[j], sb + (wn * 32 + j * 16) * HLDS + kk * 16, HLDS);
            #pragma unroll
            for (int i = 0; i < 4; i++)
                #pragma unroll
                for (int j = 0; j < 2; j++)
                    wmma::mma_sync(acc[i][j], af[i], bf[j], acc[i][j]);
        }
    }

    // direct fp16 store: float acc -> half acc fragment (same element mapping)
    #pragma unroll
    for (int i = 0; i < 4; i++)
        #pragma unroll
        for (int j = 0; j < 2; j++) {
            CHH h;
            #pragma unroll
            for (int e = 0; e < h.num_elements; e++)
                h.x[e] = __float2half_rn(acc[i][j].x[e]);
            wmma::store_matrix_sync(C + (size_t)(m0 + wm * 64 + i * 16) * HH + n0 + wn * 32 + j * 16,
                                    h, HH, wmma::mem_row_major);
        }
}

// ---------------- readout GEMM (fp16 MMA, fused bias, direct to d_out) -------
__global__ __launch_bounds__(256, 2) void gemm_readout(
    const __half* __restrict__ A, const __half* __restrict__ B, float* __restrict__ C,
    int Nvalid, int K, int ldc, const float* __restrict__ bias)
{
    extern __shared__ __half smh[];
    float* smf = (float*)smh;
    int t = threadIdx.x;
    int m0 = blockIdx.y * BM, n0 = blockIdx.x * BN;
    int w = t >> 5, wm = w & 1, wn = w >> 1;
    int KT = K / HBK;

    CFH acc[4][2];
    #pragma unroll
    for (int i = 0; i < 4; i++)
        #pragma unroll
        for (int j = 0; j < 2; j++) wmma::fill_fragment(acc[i][j], 0.0f);

    h_issue(A, B, smh, t, m0, n0, K, Nvalid, 0, 0);
    h_issue(A, B, smh, t, m0, n0, K, Nvalid, 1, 1);

    for (int kt = 0; kt < KT; kt++) {
        if (kt == KT - 1) asm volatile("cp.async.wait_group 0;\n" ::: "memory");
        else              asm volatile("cp.async.wait_group 1;\n" ::: "memory");
        __syncthreads();
        if (kt + 2 < KT)
            h_issue(A, B, smh, t, m0, n0, K, Nvalid, kt + 2, (kt + 2) % 3);

        const __half* sa = smh + (kt % 3) * HSTRIDE;
        const __half* sb = sa + BM * HLDS;
        #pragma unroll
        for (int kk = 0; kk < HBK / 16; kk++) {
            AFH af[4]; BFH bf[2];
            #pragma unroll
            for (int i = 0; i < 4; i++)
                wmma::load_matrix_sync(af[i], sa + (wm * 64 + i * 16) * HLDS + kk * 16, HLDS);
            #pragma unroll
            for (int j = 0; j < 2; j++)
                wmma::load_matrix_sync(bf[j], sb + (wn * 32 + j * 16) * HLDS + kk * 16, HLDS);
            #pragma unroll
            for (int i = 0; i < 4; i++)
                #pragma unroll
                for (int j = 0; j < 2; j++)
                    wmma::mma_sync(acc[i][j], af[i], bf[j], acc[i][j]);
        }
    }

    __syncthreads();
    float* tile = smf;   // 128 x 132 staging
    #pragma unroll
    for (int i = 0; i < 4; i++)
        #pragma unroll
        for (int j = 0; j < 2; j++)
            wmma::store_matrix_sync(tile + (wm * 64 + i * 16) * 132 + wn * 32 + j * 16,
                                    acc[i][j], 132, wmma::mem_row_major);
    __syncthreads();
    for (int idx = t; idx < BM * BN; idx += 256) {
        int r = idx >> 7, c = idx & 127;
        int col = n0 + c;
        if (col < Nvalid)
            C[(size_t)(m0 + r) * ldc + col] = tile[r * 132 + c] + bias[col];
    }
}

// ---------------- persistent middle (fp16 matmuls, fp16 agg input) -----------
#define MID_GRID 148
constexpr int MID_SMEM_BYTES = (2 * 256 * 68 + 256 + 64 + 64) * 4 + (256 * 72 + 3 * 64 * 72) * 2;

__global__ __launch_bounds__(512) void middle_kernel(
    const float* __restrict__ V_slow, const float* __restrict__ sem_mem,
    const float* __restrict__ mix_w, const float* __restrict__ mix_b,
    const float* __restrict__ q_w, const float* __restrict__ q_b)
{
    extern __shared__ float smem_[];
    float* fA  = smem_;                 // y_pred -> v_pred
    float* fB  = fA + 256 * 68;         // v -> Q
    float* sKb = fB + 256 * 68;         // 256
    float* sqb = sKb + 256;             // 64
    float* smw = sqb + 64;              // 64
    __half* hA = (__half*)(smw + 64);   // agg -> y(h) -> cell(h)   256*72
    __half* hV = hA + 256 * 72;
    __half* hS = hV + 64 * 72;
    __half* hQ = hS + 64 * 72;

    int t = threadIdx.x;
    int w = t >> 5;
    int rb = (w >> 1) * 32;
    int cb = (w & 1) * 32;
    int n2 = t >> 1, dh = (t & 1) * 32;

    for (int i = t; i < 64 * 64; i += 512) {
        int r = i >> 6, c2 = i & 63;
        hV[r * 72 + c2] = __float2half_rn(V_slow[i]);
        hS[r * 72 + c2] = __float2half_rn(sem_mem[i]);
        hQ[r * 72 + c2] = __float2half_rn(q_w[i]);
    }
    if (t < 256) sKb[t] = g_K[t];
    if (t < 64) { sqb[t] = q_b[t]; smw[t] = mix_w[t]; }
    float mixb = mix_b[0];

    const float4* bp_ = (const float4*)g_bin2;

    // prefetch first batch (fp16: 16384 halves = 2048 uint4)
    int b = blockIdx.x;
    uint4 pre[4];
    {
        const uint4* np_ = (const uint4*)(g_nodes_h + (size_t)b * HH);
        #pragma unroll
        for (int j = 0; j < 4; j++) pre[j] = np_[t + j * 512];
    }

    while (b < BB) {
        int nb = b + MID_GRID;
        __syncthreads();

        // agg(h) + bias -> hA (fp16)
        #pragma unroll
        for (int j = 0; j < 4; j++) {
            int i = t + j * 512;             // uint4 index, 8 halves each
            int n = i >> 3, d8 = (i & 7) * 8;
            const __half2* hp = (const __half2*)&pre[j];
            float4 b0 = bp_[i * 2], b1 = bp_[i * 2 + 1];
            __half2* dst = (__half2*)&hA[n * 72 + d8];
            float2 f0 = __half22float2(hp[0]);
            float2 f1 = __half22float2(hp[1]);
            float2 f2 = __half22float2(hp[2]);
            float2 f3 = __half22float2(hp[3]);
            dst[0] = __floats2half2_rn(f0.x + b0.x, f0.y + b0.y);
            dst[1] = __floats2half2_rn(f1.x + b0.z, f1.y + b0.w);
            dst[2] = __floats2half2_rn(f2.x + b1.x, f2.y + b1.y);
            dst[3] = __floats2half2_rn(f3.x + b1.z, f3.y + b1.w);
        }
        __syncthreads();

        // v = clip(agg @ V^T) -> fB, y = clip(agg @ S^T) -> fA
        {
            CFH vf[2][2], yf[2][2];
            #pragma unroll
            for (int i = 0; i < 2; i++)
                #pragma unroll
                for (int j = 0; j < 2; j++) { wmma::fill_fragment(vf[i][j], 0.f); wmma::fill_fragment(yf[i][j], 0.f); }
            #pragma unroll
            for (int kk = 0; kk < 4; kk++) {
                AFH a0, a1; BFH bv0, bv1, bs0, bs1;
                wmma::load_matrix_sync(a0, &hA[(rb     ) * 72 + kk * 16], 72);
                wmma::load_matrix_sync(a1, &hA[(rb + 16) * 72 + kk * 16], 72);
                wmma::load_matrix_sync(bv0, &hV[(cb     ) * 72 + kk * 16], 72);
                wmma::load_matrix_sync(bv1, &hV[(cb + 16) * 72 + kk * 16], 72);
                wmma::load_matrix_sync(bs0, &hS[(cb     ) * 72 + kk * 16], 72);
                wmma::load_matrix_sync(bs1, &hS[(cb + 16) * 72 + kk * 16], 72);
                wmma::mma_sync(vf[0][0], a0, bv0, vf[0][0]);
                wmma::mma_sync(vf[0][1], a0, bv1, vf[0][1]);
                wmma::mma_sync(vf[1][0], a1, bv0, vf[1][0]);
                wmma::mma_sync(vf[1][1], a1, bv1, vf[1][1]);
                wmma::mma_sync(yf[0][0], a0, bs0, yf[0][0]);
                wmma::mma_sync(yf[0][1], a0, bs1, yf[0][1]);
                wmma::mma_sync(yf[1][0], a1, bs0, yf[1][0]);
                wmma::mma_sync(yf[1][1], a1, bs1, yf[1][1]);
            }
            #pragma unroll
            for (int i = 0; i < 2; i++)
                #pragma unroll
                for (int j = 0; j < 2; j++) {
                    #pragma unroll
                    for (int e = 0; e < 8; e++) {
                        vf[i][j].x[e] = clip3(vf[i][j].x[e]);
                        yf[i][j].x[e] = clip3(yf[i][j].x[e]);
                    }
                    wmma::store_matrix_sync(&fA[(rb + i * 16) * 68 + cb + j * 16], yf[i][j], 68, wmma::mem_row_major);
                    wmma::store_matrix_sync(&fB[(rb + i * 16) * 68 + cb + j * 16], vf[i][j], 68, wmma::mem_row_major);
                }
        }
        __syncthreads();

        // mix = sigmoid(v . mix_w + mix_b); y: fA -> hA (fp16)
        float m;
        {
            float acc2 = 0.f;
            const float* vp = &fB[n2 * 68 + dh];
            #pragma unroll
            for (int d = 0; d < 32; d++) acc2 += vp[d] * smw[dh + d];
            acc2 += __shfl_xor_sync(0xffffffffu, acc2, 1);
            m = sigmoidf_(acc2 + mixb);
            const float* ya = &fA[n2 * 68 + dh];
            __half2* dst = (__half2*)&hA[n2 * 72 + dh];
            #pragma unroll
            for (int d = 0; d < 16; d++)
                dst[d] = __floats2half2_rn(ya[d * 2], ya[d * 2 + 1]);
        }
        __syncthreads();

        // v_pred = clip(y(h) @ V^T) -> fA
        {
            CFH pf[2][2];
            #pragma unroll
            for (int i = 0; i < 2; i++)
                #pragma unroll
                for (int j = 0; j < 2; j++) wmma::fill_fragment(pf[i][j], 0.f);
            #pragma unroll
            for (int kk = 0; kk < 4; kk++) {
                AFH a0, a1; BFH bv0, bv1;
                wmma::load_matrix_sync(a0, &hA[(rb     ) * 72 + kk * 16], 72);
                wmma::load_matrix_sync(a1, &hA[(rb + 16) * 72 + kk * 16], 72);
                wmma::load_matrix_sync(bv0, &hV[(cb     ) * 72 + kk * 16], 72);
                wmma::load_matrix_sync(bv1, &hV[(cb + 16) * 72 + kk * 16], 72);
                wmma::mma_sync(pf[0][0], a0, bv0, pf[0][0]);
                wmma::mma_sync(pf[0][1], a0, bv1, pf[0][1]);
                wmma::mma_sync(pf[1][0], a1, bv0, pf[1][0]);
                wmma::mma_sync(pf[1][1], a1, bv1, pf[1][1]);
            }
            #pragma unroll
            for (int i = 0; i < 2; i++)
                #pragma unroll
                for (int j = 0; j < 2; j++) {
                    #pragma unroll
                    for (int e = 0; e < 8; e++) pf[i][j].x[e] = clip3(pf[i][j].x[e]);
                    wmma::store_matrix_sync(&fA[(rb + i * 16) * 68 + cb + j * 16], pf[i][j], 68, wmma::mem_row_major);
                }
        }
        __syncthreads();

        // cell = fp16(clip(m*v + (1-m)*v_pred)) -> hA
        {
            const float* va = &fB[n2 * 68 + dh];
            const float* pa = &fA[n2 * 68 + dh];
            __half2* dst = (__half2*)&hA[n2 * 72 + dh];
            #pragma unroll
            for (int d = 0; d < 16; d++) {
                float c0 = clip3(m * va[d * 2]     + (1.f - m) * pa[d * 2]);
                float c1 = clip3(m * va[d * 2 + 1] + (1.f - m) * pa[d * 2 + 1]);
                dst[d] = __floats2half2_rn(c0, c1);
            }
        }
        __syncthreads();

        // Q = cell(h) @ q_w^T -> fB
        {
            CFH qf[2][2];
            #pragma unroll
            for (int i = 0; i < 2; i++)
                #pragma unroll
                for (int j = 0; j < 2; j++) wmma::fill_fragment(qf[i][j], 0.f);
            #pragma unroll
            for (int kk = 0; kk < 4; kk++) {
                AFH a0, a1; BFH bq0, bq1;
                wmma::load_matrix_sync(a0, &hA[(rb     ) * 72 + kk * 16], 72);
                wmma::load_matrix_sync(a1, &hA[(rb + 16) * 72 + kk * 16], 72);
                wmma::load_matrix_sync(bq0, &hQ[(cb     ) * 72 + kk * 16], 72);
                wmma::load_matrix_sync(bq1, &hQ[(cb + 16) * 72 + kk * 16], 72);
                wmma::mma_sync(qf[0][0], a0, bq0, qf[0][0]);
                wmma::mma_sync(qf[0][1], a0, bq1, qf[0][1]);
                wmma::mma_sync(qf[1][0], a1, bq0, qf[1][0]);
                wmma::mma_sync(qf[1][1], a1, bq1, qf[1][1]);
            }
            #pragma unroll
            for (int i = 0; i < 2; i++)
                #pragma unroll
                for (int j = 0; j < 2; j++)
                    wmma::store_matrix_sync(&fB[(rb + i * 16) * 68 + cb + j * 16], qf[i][j], 68, wmma::mem_row_major);
        }
        __syncthreads();

        // prefetch next batch (hidden under attention + loop-top)
        if (nb < BB) {
            const uint4* np_ = (const uint4*)(g_nodes_h + (size_t)nb * HH);
            #pragma unroll
            for (int j = 0; j < 4; j++) pre[j] = np_[t + j * 512];
        }

        // attention: softmax -> g_wh (fp16)
        {
            float qv[32];
            #pragma unroll
            for (int d = 0; d < 32; d++) qv[d] = fB[n2 * 68 + dh + d] + sqb[dh + d];
            float s0 = 0.f, s1 = 0.f, s2 = 0.f, s3 = 0.f;
            #pragma unroll
            for (int d = 0; d < 32; d++) {
                s0 += qv[d] * sKb[dh + d];
                s1 += qv[d] * sKb[64 + dh + d];
                s2 += qv[d] * sKb[128 + dh + d];
                s3 += qv[d] * sKb[192 + dh + d];
            }
            s0 += __shfl_xor_sync(0xffffffffu, s0, 1);
            s1 += __shfl_xor_sync(0xffffffffu, s1, 1);
            s2 += __shfl_xor_sync(0xffffffffu, s2, 1);
            s3 += __shfl_xor_sync(0xffffffffu, s3, 1);
            if ((t & 1) == 0) {
                s0 *= 0.125f; s1 *= 0.125f; s2 *= 0.125f; s3 *= 0.125f;
                float mx = fmaxf(fmaxf(s0, s1), fmaxf(s2, s3));
                float e0 = expf(s0 - mx), e1 = expf(s1 - mx), e2 = expf(s2 - mx), e3 = expf(s3 - mx);
                float inv = 1.f / (e0 + e1 + e2 + e3);
                __half2* dst = (__half2*)(g_wh + (size_t)b * CPAD + n2 * 4);
                dst[0] = __floats2half2_rn(e0 * inv, e1 * inv);
                dst[1] = __floats2half2_rn(e2 * inv, e3 * inv);
            }
        }

        b = nb;
    }
}

// ---------------- launcher ---------------------------------------------------
extern "C" void kernel_launch(void* const* d_in, const int* in_sizes, int n_in,
                              void* d_out, int out_size)
{
    (void)in_sizes; (void)n_in; (void)out_size;
    const float* x      = (const float*)d_in[0];
    const float* W_in   = (const float*)d_in[1];
    const float* b_in   = (const float*)d_in[2];
    const float* adj_w  = (const float*)d_in[3];
    const float* V_slow = (const float*)d_in[5];
    const float* sem    = (const float*)d_in[6];
    const float* mix_w  = (const float*)d_in[7];
    const float* mix_b  = (const float*)d_in[8];
    const float* basis  = (const float*)d_in[9];
    const float* q_w    = (const float*)d_in[10];
    const float* q_b    = (const float*)d_in[11];
    const float* k_w    = (const float*)d_in[12];
    const float* k_b    = (const float*)d_in[13];
    const float* W_out  = (const float*)d_in[14];
    const float* b_out  = (const float*)d_in[15];
    float* out = (float*)d_out;

    cudaFuncSetAttribute(gemm1_h,      cudaFuncAttributeMaxDynamicSharedMemorySize, GEMM_SMEM_H);
    cudaFuncSetAttribute(gemm_readout, cudaFuncAttributeMaxDynamicSharedMemorySize, GEMM_SMEM_H);
    cudaFuncSetAttribute(middle_kernel, cudaFuncAttributeMaxDynamicSharedMemorySize, MID_SMEM_BYTES);

    void *p_nodes = 0, *p_wh = 0, *p_mmath = 0, *p_win2h = 0, *p_xh = 0;
    cudaGetSymbolAddress(&p_nodes,  g_nodes_h);
    cudaGetSymbolAddress(&p_wh,     g_wh);
    cudaGetSymbolAddress(&p_mmath,  g_mmath);
    cudaGetSymbolAddress(&p_win2h,  g_win2h);
    cudaGetSymbolAddress(&p_xh,     g_xh);

    prep_kernel<<<1, 256>>>(adj_w, k_w, k_b, basis);
    fold_win_kernel<<<(HH * (FF / 4) + 255) / 256, 256>>>(W_in, b_in);
    round_x_kernel<<<(BB * FF / 4 + 255) / 256, 256>>>(x);
    mmat_kernel<<<(CC * NN / 2 + 7) / 8, 256>>>(W_out, basis);

    // agg = xh @ W_in'^T  (fp16 MMA, direct fp16 store)
    gemm1_h<<<dim3(HH / BN, BB / BM), 256, GEMM_SMEM_H>>>(
        (const __half*)p_xh, (const __half*)p_win2h, (__half*)p_nodes);

    // persistent middle (fp16 matmuls, fp16 agg input)
    middle_kernel<<<MID_GRID, 512, MID_SMEM_BYTES>>>(V_slow, sem, mix_w, mix_b, q_w, q_b);

    // logits = wh @ Mmat^T + b_out  (fp16 MMA, direct store to d_out)
    gemm_readout<<<dim3(CPAD / BN, BB / BM), 256, GEMM_SMEM_H>>>(
        (const __half*)p_wh, (const __half*)p_mmath, out, CC, CPAD, CC, b_out);
}

// round 14
// speedup vs baseline: 2.7749x; 1.0076x over previous
#include <cuda_runtime.h>
#include <mma.h>
#include <math.h>
#include <stdint.h>
#include <cuda_fp16.h>

using namespace nvcuda;

#define GRIDN 16
#define NN 256
#define DD 64
#define BB 4096
#define FF 512
#define HH 16384
#define CC 1000
#define CPAD 1024

// ---------------- scratch ----------------------------------------------------
__device__ __half g_nodes_h[(size_t)BB * HH];   // agg (fp16, no bias) 128 MB
__device__ __half g_xh[(size_t)BB * FF];        // x rounded to fp16
__device__ __half g_win2h[(size_t)HH * FF];     // adj-folded W_in (fp16)
__device__ float  g_bin2[HH];                   // folded b_in (fp32)
__device__ __half g_wh[(size_t)BB * CPAD];      // softmax weights (fp16)
__device__ __half g_mmath[(size_t)CC * CPAD];   // folded basis x W_out (fp16)
__device__ float  g_adjw[NN * 4];
__device__ int    g_adjn[NN * 4];
__device__ float  g_K[4 * DD];

__device__ __forceinline__ float sigmoidf_(float x) { return 1.0f / (1.0f + expf(-x)); }
__device__ __forceinline__ float clip3(float x) { return fminf(fmaxf(x, -3.0f), 3.0f); }

// ---------------- prep: adjacency rows + K = basis @ k_w^T + k_b ------------
__global__ void prep_kernel(const float* __restrict__ adjw,
                            const float* __restrict__ k_w,
                            const float* __restrict__ k_b,
                            const float* __restrict__ basis)
{
    int t = threadIdx.x;
    int r = t >> 4, c = t & 15;
    int nb[4]; int cnt = 0;
    if (r > 0)         nb[cnt++] = t - GRIDN;
    if (r < GRIDN - 1) nb[cnt++] = t + GRIDN;
    if (c > 0)         nb[cnt++] = t - 1;
    if (c < GRIDN - 1) nb[cnt++] = t + 1;

    float w[4] = {0.f, 0.f, 0.f, 0.f};
    float deg = 0.f;
    for (int j = 0; j < cnt; j++) { w[j] = sigmoidf_(adjw[t * NN + nb[j]]); deg += w[j]; }
    deg = fmaxf(deg, 1e-6f);
    int over = 0;
    for (int j = 0; j < cnt; j++) { w[j] /= deg; if (w[j] > 0.1f) over++; }
    if (over < 1) w[0] = fmaxf(w[0], 0.5f);
    for (int j = 0; j < 4; j++) {
        g_adjw[t * 4 + j] = (j < cnt) ? w[j] : 0.f;
        g_adjn[t * 4 + j] = (j < cnt) ? nb[j] : t;
    }

    int kr = t >> 6, kc = t & 63;
    float acc = k_b[kc];
    for (int d = 0; d < DD; d++) acc += basis[kr * DD + d] * k_w[kc * DD + d];
    g_K[kr * DD + kc] = acc;
}

// ---------------- combined prep2: fold_win | round_x | mmat ------------------
#define FOLD_BLKS  (HH * (FF / 4) / 256)        // 8192
#define RX_BLKS    (BB * (FF / 4) / 256)        // 2048
#define MMAT_BLKS  ((CC * NN) / 4 / 8)          // 8000 (4 rows/warp, 8 warps/blk)
#define PREP2_GRID (FOLD_BLKS + RX_BLKS + MMAT_BLKS)

__global__ void prep2_kernel(const float* __restrict__ W_in, const float* __restrict__ b_in,
                             const float* __restrict__ x,
                             const float* __restrict__ W_out, const float* __restrict__ basis)
{
    int blk = blockIdx.x;
    int t = threadIdx.x;

    if (blk < FOLD_BLKS) {
        // ---- fold adjacency into W_in / b_in (fp16-round W) ----
        int idx = blk * 256 + t;
        int row = idx >> 7, c4 = idx & 127;
        int n = row >> 6, d = row & 63;
        float w0 = g_adjw[n * 4 + 0], w1 = g_adjw[n * 4 + 1];
        float w2 = g_adjw[n * 4 + 2], w3 = g_adjw[n * 4 + 3];
        int   r0 = g_adjn[n * 4 + 0] * DD + d, r1 = g_adjn[n * 4 + 1] * DD + d;
        int   r2 = g_adjn[n * 4 + 2] * DD + d, r3 = g_adjn[n * 4 + 3] * DD + d;
        float4 a = ((const float4*)(W_in + (size_t)r0 * FF))[c4];
        float4 b = ((const float4*)(W_in + (size_t)r1 * FF))[c4];
        float4 c = ((const float4*)(W_in + (size_t)r2 * FF))[c4];
        float4 e = ((const float4*)(W_in + (size_t)r3 * FF))[c4];
        __half2 h0 = __floats2half2_rn(w0 * a.x + w1 * b.x + w2 * c.x + w3 * e.x,
                                       w0 * a.y + w1 * b.y + w2 * c.y + w3 * e.y);
        __half2 h1 = __floats2half2_rn(w0 * a.z + w1 * b.z + w2 * c.z + w3 * e.z,
                                       w0 * a.w + w1 * b.w + w2 * c.w + w3 * e.w);
        __half2* dst = (__half2*)(g_win2h + (size_t)row * FF + c4 * 4);
        dst[0] = h0; dst[1] = h1;
        if (c4 == 0)
            g_bin2[row] = w0 * b_in[r0] + w1 * b_in[r1] + w2 * b_in[r2] + w3 * b_in[r3];
    } else if (blk < FOLD_BLKS + RX_BLKS) {
        // ---- round x to fp16 ----
        int i = (blk - FOLD_BLKS) * 256 + t;
        float4 v = ((const float4*)x)[i];
        __half2* dst = (__half2*)(g_xh + (size_t)i * 4);
        dst[0] = __floats2half2_rn(v.x, v.y);
        dst[1] = __floats2half2_rn(v.z, v.w);
    } else {
        // ---- Mmat: 4 rows per warp (8 independent 128B loads in flight) ----
        int gw = ((blk - FOLD_BLKS - RX_BLKS) * 256 + t) >> 5;
        int lane = t & 31;
        int rowi = gw * 4;
        if (rowi >= CC * NN) return;
        const float* rp = W_out + (size_t)rowi * DD;
        float a0 = rp[lane],            a1 = rp[lane + 32];
        float b0 = rp[64 + lane],       b1 = rp[96 + lane];
        float c0 = rp[128 + lane],      c1 = rp[160 + lane];
        float d0 = rp[192 + lane],      d1 = rp[224 + lane];
        float ba0 = basis[lane],        ba1 = basis[lane + 32];
        float bb0 = basis[64 + lane],   bb1 = basis[96 + lane];
        float bc0 = basis[128 + lane],  bc1 = basis[160 + lane];
        float bd0 = basis[192 + lane],  bd1 = basis[224 + lane];
        float r[16];
        r[0]  = a0 * ba0 + a1 * ba1;  r[1]  = a0 * bb0 + a1 * bb1;
        r[2]  = a0 * bc0 + a1 * bc1;  r[3]  = a0 * bd0 + a1 * bd1;
        r[4]  = b0 * ba0 + b1 * ba1;  r[5]  = b0 * bb0 + b1 * bb1;
        r[6]  = b0 * bc0 + b1 * bc1;  r[7]  = b0 * bd0 + b1 * bd1;
        r[8]  = c0 * ba0 + c1 * ba1;  r[9]  = c0 * bb0 + c1 * bb1;
        r[10] = c0 * bc0 + c1 * bc1;  r[11] = c0 * bd0 + c1 * bd1;
        r[12] = d0 * ba0 + d1 * ba1;  r[13] = d0 * bb0 + d1 * bb1;
        r[14] = d0 * bc0 + d1 * bc1;  r[15] = d0 * bd0 + d1 * bd1;
        #pragma unroll
        for (int o = 16; o; o >>= 1)
            #pragma unroll
            for (int q = 0; q < 16; q++)
                r[q] += __shfl_xor_sync(0xffffffffu, r[q], o);
        if (lane == 0) {
            __half2* dd = (__half2*)(g_mmath + (size_t)rowi * 4);
            #pragma unroll
            for (int q = 0; q < 8; q++)
                dd[q] = __floats2half2_rn(r[q * 2], r[q * 2 + 1]);
        }
    }
}

// ---------------- fp16 GEMM skeleton (128x128, 256 thr, 3-stage) ------------
#define BM 128
#define BN 128
#define HBK 64
#define HLDS 72
#define HSTRIDE ((BM + BN) * HLDS)                  // halves per stage (18432)
#define GEMM_SMEM_H (3 * HSTRIDE * 2)               // 110592 B

typedef wmma::fragment<wmma::matrix_a, 16, 16, 16, __half, wmma::row_major> AFH;
typedef wmma::fragment<wmma::matrix_b, 16, 16, 16, __half, wmma::col_major> BFH;
typedef wmma::fragment<wmma::accumulator, 16, 16, 16, float> CFH;
typedef wmma::fragment<wmma::accumulator, 16, 16, 16, __half> CHH;

__device__ __forceinline__ void h_issue(const __half* A, const __half* B, __half* smh,
                                        int t, int m0, int n0, int K, int Nvalid,
                                        int kt, int s)
{
    int k0 = kt * HBK;
    __half* dstA0 = smh + s * HSTRIDE;
    __half* dstB0 = dstA0 + BM * HLDS;
    #pragma unroll
    for (int i = 0; i < 4; i++) {
        int id = t + i * 256;
        int row = id >> 3, c8 = id & 7;
        const __half* gA = A + (size_t)(m0 + row) * K + k0 + c8 * 8;
        unsigned int da = (unsigned int)__cvta_generic_to_shared(dstA0 + row * HLDS + c8 * 8);
        asm volatile("cp.async.cg.shared.global [%0], [%1], 16;\n" :: "r"(da), "l"(gA));
        int brow = n0 + row;
        const __half* gB = B + (size_t)brow * K + k0 + c8 * 8;
        unsigned int db = (unsigned int)__cvta_generic_to_shared(dstB0 + row * HLDS + c8 * 8);
        int sz = (brow < Nvalid) ? 16 : 0;
        asm volatile("cp.async.cg.shared.global [%0], [%1], 16, %2;\n" :: "r"(db), "l"(gB), "r"(sz));
    }
    asm volatile("cp.async.commit_group;\n" ::: "memory");
}

// ---------------- GEMM1: direct fp16 store (no staging) ----------------------
__global__ __launch_bounds__(256, 2) void gemm1_h(
    const __half* __restrict__ A, const __half* __restrict__ B, __half* __restrict__ C)
{
    extern __shared__ __half smh[];
    int t = threadIdx.x;
    int m0 = blockIdx.y * BM, n0 = blockIdx.x * BN;
    int w = t >> 5, wm = w & 1, wn = w >> 1;
    const int KT = FF / HBK;   // 8

    CFH acc[4][2];
    #pragma unroll
    for (int i = 0; i < 4; i++)
        #pragma unroll
        for (int j = 0; j < 2; j++) wmma::fill_fragment(acc[i][j], 0.0f);

    h_issue(A, B, smh, t, m0, n0, FF, HH, 0, 0);
    h_issue(A, B, smh, t, m0, n0, FF, HH, 1, 1);

    for (int kt = 0; kt < KT; kt++) {
        if (kt == KT - 1) asm volatile("cp.async.wait_group 0;\n" ::: "memory");
        else              asm volatile("cp.async.wait_group 1;\n" ::: "memory");
        __syncthreads();
        if (kt + 2 < KT)
            h_issue(A, B, smh, t, m0, n0, FF, HH, kt + 2, (kt + 2) % 3);

        const __half* sa = smh + (kt % 3) * HSTRIDE;
        const __half* sb = sa + BM * HLDS;
        #pragma unroll
        for (int kk = 0; kk < HBK / 16; kk++) {
            AFH af[4]; BFH bf[2];
            #pragma unroll
            for (int i = 0; i < 4; i++)
                wmma::load_matrix_sync(af[i], sa + (wm * 64 + i * 16) * HLDS + kk * 16, HLDS);
            #pragma unroll
            for (int j = 0; j < 2; j++)
                wmma::load_matrix_sync(bf[j], sb + (wn * 32 + j * 16) * HLDS + kk * 16, HLDS);
            #pragma unroll
            for (int i = 0; i < 4; i++)
                #pragma unroll
                for (int j = 0; j < 2; j++)
                    wmma::mma_sync(acc[i][j], af[i], bf[j], acc[i][j]);
        }
    }

    #pragma unroll
    for (int i = 0; i < 4; i++)
        #pragma unroll
        for (int j = 0; j < 2; j++) {
            CHH h;
            #pragma unroll
            for (int e = 0; e < h.num_elements; e++)
                h.x[e] = __float2half_rn(acc[i][j].x[e]);
            wmma::store_matrix_sync(C + (size_t)(m0 + wm * 64 + i * 16) * HH + n0 + wn * 32 + j * 16,
                                    h, HH, wmma::mem_row_major);
        }
}

// ---------------- readout GEMM (fp16 MMA, fused bias, direct to d_out) -------
__global__ __launch_bounds__(256, 2) void gemm_readout(
    const __half* __restrict__ A, const __half* __restrict__ B, float* __restrict__ C,
    int Nvalid, int K, int ldc, const float* __restrict__ bias)
{
    extern __shared__ __half smh[];
    float* smf = (float*)smh;
    int t = threadIdx.x;
    int m0 = blockIdx.y * BM, n0 = blockIdx.x * BN;
    int w = t >> 5, wm = w & 1, wn = w >> 1;
    int KT = K / HBK;

    CFH acc[4][2];
    #pragma unroll
    for (int i = 0; i < 4; i++)
        #pragma unroll
        for (int j = 0; j < 2; j++) wmma::fill_fragment(acc[i][j], 0.0f);

    h_issue(A, B, smh, t, m0, n0, K, Nvalid, 0, 0);
    h_issue(A, B, smh, t, m0, n0, K, Nvalid, 1, 1);

    for (int kt = 0; kt < KT; kt++) {
        if (kt == KT - 1) asm volatile("cp.async.wait_group 0;\n" ::: "memory");
        else              asm volatile("cp.async.wait_group 1;\n" ::: "memory");
        __syncthreads();
        if (kt + 2 < KT)
            h_issue(A, B, smh, t, m0, n0, K, Nvalid, kt + 2, (kt + 2) % 3);

        const __half* sa = smh + (kt % 3) * HSTRIDE;
        const __half* sb = sa + BM * HLDS;
        #pragma unroll
        for (int kk = 0; kk < HBK / 16; kk++) {
            AFH af[4]; BFH bf[2];
            #pragma unroll
            for (int i = 0; i < 4; i++)
                wmma::load_matrix_sync(af[i], sa + (wm * 64 + i * 16) * HLDS + kk * 16, HLDS);
            #pragma unroll
            for (int j = 0; j < 2; j++)
                wmma::load_matrix_sync(bf[j], sb + (wn * 32 + j * 16) * HLDS + kk * 16, HLDS);
            #pragma unroll
            for (int i = 0; i < 4; i++)
                #pragma unroll
                for (int j = 0; j < 2; j++)
                    wmma::mma_sync(acc[i][j], af[i], bf[j], acc[i][j]);
        }
    }

    __syncthreads();
    float* tile = smf;   // 128 x 132 staging
    #pragma unroll
    for (int i = 0; i < 4; i++)
        #pragma unroll
        for (int j = 0; j < 2; j++)
            wmma::store_matrix_sync(tile + (wm * 64 + i * 16) * 132 + wn * 32 + j * 16,
                                    acc[i][j], 132, wmma::mem_row_major);
    __syncthreads();
    for (int idx = t; idx < BM * BN; idx += 256) {
        int r = idx >> 7, c = idx & 127;
        int col = n0 + c;
        if (col < Nvalid)
            C[(size_t)(m0 + r) * ldc + col] = tile[r * 132 + c] + bias[col];
    }
}

// ---------------- persistent middle (fp16 matmuls, fp16 agg input) -----------
#define MID_GRID 148
constexpr int MID_SMEM_BYTES = (2 * 256 * 68 + 256 + 64 + 64) * 4 + (256 * 72 + 3 * 64 * 72) * 2;

__global__ __launch_bounds__(512) void middle_kernel(
    const float* __restrict__ V_slow, const float* __restrict__ sem_mem,
    const float* __restrict__ mix_w, const float* __restrict__ mix_b,
    const float* __restrict__ q_w, const float* __restrict__ q_b)
{
    extern __shared__ float smem_[];
    float* fA  = smem_;                 // y_pred -> v_pred
    float* fB  = fA + 256 * 68;         // v -> Q
    float* sKb = fB + 256 * 68;         // 256
    float* sqb = sKb + 256;             // 64
    float* smw = sqb + 64;              // 64
    __half* hA = (__half*)(smw + 64);   // agg -> y(h) -> cell(h)   256*72
    __half* hV = hA + 256 * 72;
    __half* hS = hV + 64 * 72;
    __half* hQ = hS + 64 * 72;

    int t = threadIdx.x;
    int w = t >> 5;
    int rb = (w >> 1) * 32;
    int cb = (w & 1) * 32;
    int n2 = t >> 1, dh = (t & 1) * 32;

    for (int i = t; i < 64 * 64; i += 512) {
        int r = i >> 6, c2 = i & 63;
        hV[r * 72 + c2] = __float2half_rn(V_slow[i]);
        hS[r * 72 + c2] = __float2half_rn(sem_mem[i]);
        hQ[r * 72 + c2] = __float2half_rn(q_w[i]);
    }
    if (t < 256) sKb[t] = g_K[t];
    if (t < 64) { sqb[t] = q_b[t]; smw[t] = mix_w[t]; }
    float mixb = mix_b[0];

    const float4* bp_ = (const float4*)g_bin2;

    int b = blockIdx.x;
    uint4 pre[4];
    {
        const uint4* np_ = (const uint4*)(g_nodes_h + (size_t)b * HH);
        #pragma unroll
        for (int j = 0; j < 4; j++) pre[j] = np_[t + j * 512];
    }

    while (b < BB) {
        int nb = b + MID_GRID;
        __syncthreads();

        // agg(h) + bias -> hA (fp16)
        #pragma unroll
        for (int j = 0; j < 4; j++) {
            int i = t + j * 512;
            int n = i >> 3, d8 = (i & 7) * 8;
            const __half2* hp = (const __half2*)&pre[j];
            float4 b0 = bp_[i * 2], b1 = bp_[i * 2 + 1];
            __half2* dst = (__half2*)&hA[n * 72 + d8];
            float2 f0 = __half22float2(hp[0]);
            float2 f1 = __half22float2(hp[1]);
            float2 f2 = __half22float2(hp[2]);
            float2 f3 = __half22float2(hp[3]);
            dst[0] = __floats2half2_rn(f0.x + b0.x, f0.y + b0.y);
            dst[1] = __floats2half2_rn(f1.x + b0.z, f1.y + b0.w);
            dst[2] = __floats2half2_rn(f2.x + b1.x, f2.y + b1.y);
            dst[3] = __floats2half2_rn(f3.x + b1.z, f3.y + b1.w);
        }
        __syncthreads();

        // v = clip(agg @ V^T) -> fB, y = clip(agg @ S^T) -> fA
        {
            CFH vf[2][2], yf[2][2];
            #pragma unroll
            for (int i = 0; i < 2; i++)
                #pragma unroll
                for (int j = 0; j < 2; j++) { wmma::fill_fragment(vf[i][j], 0.f); wmma::fill_fragment(yf[i][j], 0.f); }
            #pragma unroll
            for (int kk = 0; kk < 4; kk++) {
                AFH a0, a1; BFH bv0, bv1, bs0, bs1;
                wmma::load_matrix_sync(a0, &hA[(rb     ) * 72 + kk * 16], 72);
                wmma::load_matrix_sync(a1, &hA[(rb + 16) * 72 + kk * 16], 72);
                wmma::load_matrix_sync(bv0, &hV[(cb     ) * 72 + kk * 16], 72);
                wmma::load_matrix_sync(bv1, &hV[(cb + 16) * 72 + kk * 16], 72);
                wmma::load_matrix_sync(bs0, &hS[(cb     ) * 72 + kk * 16], 72);
                wmma::load_matrix_sync(bs1, &hS[(cb + 16) * 72 + kk * 16], 72);
                wmma::mma_sync(vf[0][0], a0, bv0, vf[0][0]);
                wmma::mma_sync(vf[0][1], a0, bv1, vf[0][1]);
                wmma::mma_sync(vf[1][0], a1, bv0, vf[1][0]);
                wmma::mma_sync(vf[1][1], a1, bv1, vf[1][1]);
                wmma::mma_sync(yf[0][0], a0, bs0, yf[0][0]);
                wmma::mma_sync(yf[0][1], a0, bs1, yf[0][1]);
                wmma::mma_sync(yf[1][0], a1, bs0, yf[1][0]);
                wmma::mma_sync(yf[1][1], a1, bs1, yf[1][1]);
            }
            #pragma unroll
            for (int i = 0; i < 2; i++)
                #pragma unroll
                for (int j = 0; j < 2; j++) {
                    #pragma unroll
                    for (int e = 0; e < 8; e++) {
                        vf[i][j].x[e] = clip3(vf[i][j].x[e]);
                        yf[i][j].x[e] = clip3(yf[i][j].x[e]);
                    }
                    wmma::store_matrix_sync(&fA[(rb + i * 16) * 68 + cb + j * 16], yf[i][j], 68, wmma::mem_row_major);
                    wmma::store_matrix_sync(&fB[(rb + i * 16) * 68 + cb + j * 16], vf[i][j], 68, wmma::mem_row_major);
                }
        }
        __syncthreads();

        // mix = sigmoid(v . mix_w + mix_b); y: fA -> hA (fp16)
        float m;
        {
            float acc2 = 0.f;
            const float* vp = &fB[n2 * 68 + dh];
            #pragma unroll
            for (int d = 0; d < 32; d++) acc2 += vp[d] * smw[dh + d];
            acc2 += __shfl_xor_sync(0xffffffffu, acc2, 1);
            m = sigmoidf_(acc2 + mixb);
            const float* ya = &fA[n2 * 68 + dh];
            __half2* dst = (__half2*)&hA[n2 * 72 + dh];
            #pragma unroll
            for (int d = 0; d < 16; d++)
                dst[d] = __floats2half2_rn(ya[d * 2], ya[d * 2 + 1]);
        }
        __syncthreads();

        // v_pred = clip(y(h) @ V^T) -> fA
        {
            CFH pf[2][2];
            #pragma unroll
            for (int i = 0; i < 2; i++)
                #pragma unroll
                for (int j = 0; j < 2; j++) wmma::fill_fragment(pf[i][j], 0.f);
            #pragma unroll
            for (int kk = 0; kk < 4; kk++) {
                AFH a0, a1; BFH bv0, bv1;
                wmma::load_matrix_sync(a0, &hA[(rb     ) * 72 + kk * 16], 72);
                wmma::load_matrix_sync(a1, &hA[(rb + 16) * 72 + kk * 16], 72);
                wmma::load_matrix_sync(bv0, &hV[(cb     ) * 72 + kk * 16], 72);
                wmma::load_matrix_sync(bv1, &hV[(cb + 16) * 72 + kk * 16], 72);
                wmma::mma_sync(pf[0][0], a0, bv0, pf[0][0]);
                wmma::mma_sync(pf[0][1], a0, bv1, pf[0][1]);
                wmma::mma_sync(pf[1][0], a1, bv0, pf[1][0]);
                wmma::mma_sync(pf[1][1], a1, bv1, pf[1][1]);
            }
            #pragma unroll
            for (int i = 0; i < 2; i++)
                #pragma unroll
                for (int j = 0; j < 2; j++) {
                    #pragma unroll
                    for (int e = 0; e < 8; e++) pf[i][j].x[e] = clip3(pf[i][j].x[e]);
                    wmma::store_matrix_sync(&fA[(rb + i * 16) * 68 + cb + j * 16], pf[i][j], 68, wmma::mem_row_major);
                }
        }
        __syncthreads();

        // cell = fp16(clip(m*v + (1-m)*v_pred)) -> hA
        {
            const float* va = &fB[n2 * 68 + dh];
            const float* pa = &fA[n2 * 68 + dh];
            __half2* dst = (__half2*)&hA[n2 * 72 + dh];
            #pragma unroll
            for (int d = 0; d < 16; d++) {
                float c0 = clip3(m * va[d * 2]     + (1.f - m) * pa[d * 2]);
                float c1 = clip3(m * va[d * 2 + 1] + (1.f - m) * pa[d * 2 + 1]);
                dst[d] = __floats2half2_rn(c0, c1);
            }
        }
        __syncthreads();

        // Q = cell(h) @ q_w^T -> fB
        {
            CFH qf[2][2];
            #pragma unroll
            for (int i = 0; i < 2; i++)
                #pragma unroll
                for (int j = 0; j < 2; j++) wmma::fill_fragment(qf[i][j], 0.f);
            #pragma unroll
            for (int kk = 0; kk < 4; kk++) {
                AFH a0, a1; BFH bq0, bq1;
                wmma::load_matrix_sync(a0, &hA[(rb     ) * 72 + kk * 16], 72);
                wmma::load_matrix_sync(a1, &hA[(rb + 16) * 72 + kk * 16], 72);
                wmma::load_matrix_sync(bq0, &hQ[(cb     ) * 72 + kk * 16], 72);
                wmma::load_matrix_sync(bq1, &hQ[(cb + 16) * 72 + kk * 16], 72);
                wmma::mma_sync(qf[0][0], a0, bq0, qf[0][0]);
                wmma::mma_sync(qf[0][1], a0, bq1, qf[0][1]);
                wmma::mma_sync(qf[1][0], a1, bq0, qf[1][0]);
                wmma::mma_sync(qf[1][1], a1, bq1, qf[1][1]);
            }
            #pragma unroll
            for (int i = 0; i < 2; i++)
                #pragma unroll
                for (int j = 0; j < 2; j++)
                    wmma::store_matrix_sync(&fB[(rb + i * 16) * 68 + cb + j * 16], qf[i][j], 68, wmma::mem_row_major);
        }
        __syncthreads();

        // prefetch next batch (hidden under attention + loop-top)
        if (nb < BB) {
            const uint4* np_ = (const uint4*)(g_nodes_h + (size_t)nb * HH);
            #pragma unroll
            for (int j = 0; j < 4; j++) pre[j] = np_[t + j * 512];
        }

        // attention: softmax -> g_wh (fp16)
        {
            float qv[32];
            #pragma unroll
            for (int d = 0; d < 32; d++) qv[d] = fB[n2 * 68 + dh + d] + sqb[dh + d];
            float s0 = 0.f, s1 = 0.f, s2 = 0.f, s3 = 0.f;
            #pragma unroll
            for (int d = 0; d < 32; d++) {
                s0 += qv[d] * sKb[dh + d];
                s1 += qv[d] * sKb[64 + dh + d];
                s2 += qv[d] * sKb[128 + dh + d];
                s3 += qv[d] * sKb[192 + dh + d];
            }
            s0 += __shfl_xor_sync(0xffffffffu, s0, 1);
            s1 += __shfl_xor_sync(0xffffffffu, s1, 1);
            s2 += __shfl_xor_sync(0xffffffffu, s2, 1);
            s3 += __shfl_xor_sync(0xffffffffu, s3, 1);
            if ((t & 1) == 0) {
                s0 *= 0.125f; s1 *= 0.125f; s2 *= 0.125f; s3 *= 0.125f;
                float mx = fmaxf(fmaxf(s0, s1), fmaxf(s2, s3));
                float e0 = expf(s0 - mx), e1 = expf(s1 - mx), e2 = expf(s2 - mx), e3 = expf(s3 - mx);
                float inv = 1.f / (e0 + e1 + e2 + e3);
                __half2* dst = (__half2*)(g_wh + (size_t)b * CPAD + n2 * 4);
                dst[0] = __floats2half2_rn(e0 * inv, e1 * inv);
                dst[1] = __floats2half2_rn(e2 * inv, e3 * inv);
            }
        }

        b = nb;
    }
}

// ---------------- launcher ---------------------------------------------------
extern "C" void kernel_launch(void* const* d_in, const int* in_sizes, int n_in,
                              void* d_out, int out_size)
{
    (void)in_sizes; (void)n_in; (void)out_size;
    const float* x      = (const float*)d_in[0];
    const float* W_in   = (const float*)d_in[1];
    const float* b_in   = (const float*)d_in[2];
    const float* adj_w  = (const float*)d_in[3];
    const float* V_slow = (const float*)d_in[5];
    const float* sem    = (const float*)d_in[6];
    const float* mix_w  = (const float*)d_in[7];
    const float* mix_b  = (const float*)d_in[8];
    const float* basis  = (const float*)d_in[9];
    const float* q_w    = (const float*)d_in[10];
    const float* q_b    = (const float*)d_in[11];
    const float* k_w    = (const float*)d_in[12];
    const float* k_b    = (const float*)d_in[13];
    const float* W_out  = (const float*)d_in[14];
    const float* b_out  = (const float*)d_in[15];
    float* out = (float*)d_out;

    cudaFuncSetAttribute(gemm1_h,      cudaFuncAttributeMaxDynamicSharedMemorySize, GEMM_SMEM_H);
    cudaFuncSetAttribute(gemm_readout, cudaFuncAttributeMaxDynamicSharedMemorySize, GEMM_SMEM_H);
    cudaFuncSetAttribute(middle_kernel, cudaFuncAttributeMaxDynamicSharedMemorySize, MID_SMEM_BYTES);

    void *p_nodes = 0, *p_wh = 0, *p_mmath = 0, *p_win2h = 0, *p_xh = 0;
    cudaGetSymbolAddress(&p_nodes,  g_nodes_h);
    cudaGetSymbolAddress(&p_wh,     g_wh);
    cudaGetSymbolAddress(&p_mmath,  g_mmath);
    cudaGetSymbolAddress(&p_win2h,  g_win2h);
    cudaGetSymbolAddress(&p_xh,     g_xh);

    prep_kernel<<<1, 256>>>(adj_w, k_w, k_b, basis);
    // fold_win | round_x | mmat fused into one partitioned launch
    prep2_kernel<<<PREP2_GRID, 256>>>(W_in, b_in, x, W_out, basis);

    // agg = xh @ W_in'^T  (fp16 MMA, direct fp16 store)
    gemm1_h<<<dim3(HH / BN, BB / BM), 256, GEMM_SMEM_H>>>(
        (const __half*)p_xh, (const __half*)p_win2h, (__half*)p_nodes);

    // persistent middle (fp16 matmuls, fp16 agg input)
    middle_kernel<<<MID_GRID, 512, MID_SMEM_BYTES>>>(V_slow, sem, mix_w, mix_b, q_w, q_b);

    // logits = wh @ Mmat^T + b_out  (fp16 MMA, direct store to d_out)
    gemm_readout<<<dim3(CPAD / BN, BB / BM), 256, GEMM_SMEM_H>>>(
        (const __half*)p_wh, (const __half*)p_mmath, out, CC, CPAD, CC, b_out);
}

// round 15
// speedup vs baseline: 3.4384x; 1.2391x over previous
#include <cuda_runtime.h>
#include <mma.h>
#include <math.h>
#include <stdint.h>
#include <cuda_fp16.h>

using namespace nvcuda;

#define GRIDN 16
#define NN 256
#define DD 64
#define BB 4096
#define FF 512
#define HH 16384
#define CC 1000
#define CPAD 1024

// ---------------- scratch ----------------------------------------------------
__device__ __half g_nodes_h[(size_t)BB * HH];   // agg (fp16, no bias) 128 MB
__device__ __half g_xh[(size_t)BB * FF];        // x rounded to fp16
__device__ __half g_win2h[(size_t)HH * FF];     // adj-folded W_in (fp16)
__device__ float  g_bin2[HH];                   // folded b_in (fp32)
__device__ __half g_wh[(size_t)BB * CPAD];      // softmax weights (fp16)
__device__ __half g_mmath[(size_t)CC * CPAD];   // folded basis x W_out (fp16)
__device__ float  g_adjw[NN * 4];
__device__ int    g_adjn[NN * 4];
__device__ float  g_K[4 * DD];

__device__ __forceinline__ float sigmoidf_(float x) { return 1.0f / (1.0f + expf(-x)); }
__device__ __forceinline__ float clip3(float x) { return fminf(fmaxf(x, -3.0f), 3.0f); }

// ---------------- prep: adjacency rows + K = basis @ k_w^T + k_b ------------
__global__ void prep_kernel(const float* __restrict__ adjw,
                            const float* __restrict__ k_w,
                            const float* __restrict__ k_b,
                            const float* __restrict__ basis)
{
    int t = threadIdx.x;
    int r = t >> 4, c = t & 15;
    int nb[4]; int cnt = 0;
    if (r > 0)         nb[cnt++] = t - GRIDN;
    if (r < GRIDN - 1) nb[cnt++] = t + GRIDN;
    if (c > 0)         nb[cnt++] = t - 1;
    if (c < GRIDN - 1) nb[cnt++] = t + 1;

    float w[4] = {0.f, 0.f, 0.f, 0.f};
    float deg = 0.f;
    for (int j = 0; j < cnt; j++) { w[j] = sigmoidf_(adjw[t * NN + nb[j]]); deg += w[j]; }
    deg = fmaxf(deg, 1e-6f);
    int over = 0;
    for (int j = 0; j < cnt; j++) { w[j] /= deg; if (w[j] > 0.1f) over++; }
    if (over < 1) w[0] = fmaxf(w[0], 0.5f);
    for (int j = 0; j < 4; j++) {
        g_adjw[t * 4 + j] = (j < cnt) ? w[j] : 0.f;
        g_adjn[t * 4 + j] = (j < cnt) ? nb[j] : t;
    }

    int kr = t >> 6, kc = t & 63;
    float acc = k_b[kc];
    for (int d = 0; d < DD; d++) acc += basis[kr * DD + d] * k_w[kc * DD + d];
    g_K[kr * DD + kc] = acc;
}

// ---------------- combined prep2: fold_win | round_x | mmat ------------------
#define FOLD_BLKS  (HH * (FF / 4) / 256)        // 8192
#define RX_BLKS    (BB * (FF / 4) / 256)        // 2048
#define MMAT_BLKS  ((CC * NN) / 4 / 8)          // 8000
#define PREP2_GRID (FOLD_BLKS + RX_BLKS + MMAT_BLKS)

__global__ void prep2_kernel(const float* __restrict__ W_in, const float* __restrict__ b_in,
                             const float* __restrict__ x,
                             const float* __restrict__ W_out, const float* __restrict__ basis)
{
    int blk = blockIdx.x;
    int t = threadIdx.x;

    if (blk < FOLD_BLKS) {
        int idx = blk * 256 + t;
        int row = idx >> 7, c4 = idx & 127;
        int n = row >> 6, d = row & 63;
        float w0 = g_adjw[n * 4 + 0], w1 = g_adjw[n * 4 + 1];
        float w2 = g_adjw[n * 4 + 2], w3 = g_adjw[n * 4 + 3];
        int   r0 = g_adjn[n * 4 + 0] * DD + d, r1 = g_adjn[n * 4 + 1] * DD + d;
        int   r2 = g_adjn[n * 4 + 2] * DD + d, r3 = g_adjn[n * 4 + 3] * DD + d;
        float4 a = ((const float4*)(W_in + (size_t)r0 * FF))[c4];
        float4 b = ((const float4*)(W_in + (size_t)r1 * FF))[c4];
        float4 c = ((const float4*)(W_in + (size_t)r2 * FF))[c4];
        float4 e = ((const float4*)(W_in + (size_t)r3 * FF))[c4];
        __half2 h0 = __floats2half2_rn(w0 * a.x + w1 * b.x + w2 * c.x + w3 * e.x,
                                       w0 * a.y + w1 * b.y + w2 * c.y + w3 * e.y);
        __half2 h1 = __floats2half2_rn(w0 * a.z + w1 * b.z + w2 * c.z + w3 * e.z,
                                       w0 * a.w + w1 * b.w + w2 * c.w + w3 * e.w);
        __half2* dst = (__half2*)(g_win2h + (size_t)row * FF + c4 * 4);
        dst[0] = h0; dst[1] = h1;
        if (c4 == 0)
            g_bin2[row] = w0 * b_in[r0] + w1 * b_in[r1] + w2 * b_in[r2] + w3 * b_in[r3];
    } else if (blk < FOLD_BLKS + RX_BLKS) {
        int i = (blk - FOLD_BLKS) * 256 + t;
        float4 v = ((const float4*)x)[i];
        __half2* dst = (__half2*)(g_xh + (size_t)i * 4);
        dst[0] = __floats2half2_rn(v.x, v.y);
        dst[1] = __floats2half2_rn(v.z, v.w);
    } else {
        int gw = ((blk - FOLD_BLKS - RX_BLKS) * 256 + t) >> 5;
        int lane = t & 31;
        int rowi = gw * 4;
        if (rowi >= CC * NN) return;
        const float* rp = W_out + (size_t)rowi * DD;
        float a0 = rp[lane],            a1 = rp[lane + 32];
        float b0 = rp[64 + lane],       b1 = rp[96 + lane];
        float c0 = rp[128 + lane],      c1 = rp[160 + lane];
        float d0 = rp[192 + lane],      d1 = rp[224 + lane];
        float ba0 = basis[lane],        ba1 = basis[lane + 32];
        float bb0 = basis[64 + lane],   bb1 = basis[96 + lane];
        float bc0 = basis[128 + lane],  bc1 = basis[160 + lane];
        float bd0 = basis[192 + lane],  bd1 = basis[224 + lane];
        float r[16];
        r[0]  = a0 * ba0 + a1 * ba1;  r[1]  = a0 * bb0 + a1 * bb1;
        r[2]  = a0 * bc0 + a1 * bc1;  r[3]  = a0 * bd0 + a1 * bd1;
        r[4]  = b0 * ba0 + b1 * ba1;  r[5]  = b0 * bb0 + b1 * bb1;
        r[6]  = b0 * bc0 + b1 * bc1;  r[7]  = b0 * bd0 + b1 * bd1;
        r[8]  = c0 * ba0 + c1 * ba1;  r[9]  = c0 * bb0 + c1 * bb1;
        r[10] = c0 * bc0 + c1 * bc1;  r[11] = c0 * bd0 + c1 * bd1;
        r[12] = d0 * ba0 + d1 * ba1;  r[13] = d0 * bb0 + d1 * bb1;
        r[14] = d0 * bc0 + d1 * bc1;  r[15] = d0 * bd0 + d1 * bd1;
        #pragma unroll
        for (int o = 16; o; o >>= 1)
            #pragma unroll
            for (int q = 0; q < 16; q++)
                r[q] += __shfl_xor_sync(0xffffffffu, r[q], o);
        if (lane == 0) {
            __half2* dd = (__half2*)(g_mmath + (size_t)rowi * 4);
            #pragma unroll
            for (int q = 0; q < 8; q++)
                dd[q] = __floats2half2_rn(r[q * 2], r[q * 2 + 1]);
        }
    }
}

// ---------------- fp16 GEMM skeleton (128x128, 256 thr, 3-stage) ------------
#define BM 128
#define BN 128
#define HBK 64
#define HLDS 72
#define HSTRIDE ((BM + BN) * HLDS)
#define GEMM_SMEM_H (3 * HSTRIDE * 2)               // 110592 B

typedef wmma::fragment<wmma::matrix_a, 16, 16, 16, __half, wmma::row_major> AFH;
typedef wmma::fragment<wmma::matrix_b, 16, 16, 16, __half, wmma::col_major> BFH;
typedef wmma::fragment<wmma::accumulator, 16, 16, 16, float> CFH;
typedef wmma::fragment<wmma::accumulator, 16, 16, 16, __half> CHH;

__device__ __forceinline__ void h_issue(const __half* A, const __half* B, __half* smh,
                                        int t, int m0, int n0, int K, int Nvalid,
                                        int kt, int s)
{
    int k0 = kt * HBK;
    __half* dstA0 = smh + s * HSTRIDE;
    __half* dstB0 = dstA0 + BM * HLDS;
    #pragma unroll
    for (int i = 0; i < 4; i++) {
        int id = t + i * 256;
        int row = id >> 3, c8 = id & 7;
        const __half* gA = A + (size_t)(m0 + row) * K + k0 + c8 * 8;
        unsigned int da = (unsigned int)__cvta_generic_to_shared(dstA0 + row * HLDS + c8 * 8);
        asm volatile("cp.async.cg.shared.global [%0], [%1], 16;\n" :: "r"(da), "l"(gA));
        int brow = n0 + row;
        const __half* gB = B + (size_t)brow * K + k0 + c8 * 8;
        unsigned int db = (unsigned int)__cvta_generic_to_shared(dstB0 + row * HLDS + c8 * 8);
        int sz = (brow < Nvalid) ? 16 : 0;
        asm volatile("cp.async.cg.shared.global [%0], [%1], 16, %2;\n" :: "r"(db), "l"(gB), "r"(sz));
    }
    asm volatile("cp.async.commit_group;\n" ::: "memory");
}

// ---------------- GEMM1: direct fp16 store ------------------------------------
__global__ __launch_bounds__(256, 2) void gemm1_h(
    const __half* __restrict__ A, const __half* __restrict__ B, __half* __restrict__ C)
{
    extern __shared__ __half smh[];
    int t = threadIdx.x;
    int m0 = blockIdx.y * BM, n0 = blockIdx.x * BN;
    int w = t >> 5, wm = w & 1, wn = w >> 1;
    const int KT = FF / HBK;

    CFH acc[4][2];
    #pragma unroll
    for (int i = 0; i < 4; i++)
        #pragma unroll
        for (int j = 0; j < 2; j++) wmma::fill_fragment(acc[i][j], 0.0f);

    h_issue(A, B, smh, t, m0, n0, FF, HH, 0, 0);
    h_issue(A, B, smh, t, m0, n0, FF, HH, 1, 1);

    for (int kt = 0; kt < KT; kt++) {
        if (kt == KT - 1) asm volatile("cp.async.wait_group 0;\n" ::: "memory");
        else              asm volatile("cp.async.wait_group 1;\n" ::: "memory");
        __syncthreads();
        if (kt + 2 < KT)
            h_issue(A, B, smh, t, m0, n0, FF, HH, kt + 2, (kt + 2) % 3);

        const __half* sa = smh + (kt % 3) * HSTRIDE;
        const __half* sb = sa + BM * HLDS;
        #pragma unroll
        for (int kk = 0; kk < HBK / 16; kk++) {
            AFH af[4]; BFH bf[2];
            #pragma unroll
            for (int i = 0; i < 4; i++)
                wmma::load_matrix_sync(af[i], sa + (wm * 64 + i * 16) * HLDS + kk * 16, HLDS);
            #pragma unroll
            for (int j = 0; j < 2; j++)
                wmma::load_matrix_sync(bf[j], sb + (wn * 32 + j * 16) * HLDS + kk * 16, HLDS);
            #pragma unroll
            for (int i = 0; i < 4; i++)
                #pragma unroll
                for (int j = 0; j < 2; j++)
                    wmma::mma_sync(acc[i][j], af[i], bf[j], acc[i][j]);
        }
    }

    #pragma unroll
    for (int i = 0; i < 4; i++)
        #pragma unroll
        for (int j = 0; j < 2; j++) {
            CHH h;
            #pragma unroll
            for (int e = 0; e < h.num_elements; e++)
                h.x[e] = __float2half_rn(acc[i][j].x[e]);
            wmma::store_matrix_sync(C + (size_t)(m0 + wm * 64 + i * 16) * HH + n0 + wn * 32 + j * 16,
                                    h, HH, wmma::mem_row_major);
        }
}

// ---------------- readout GEMM (fp16 MMA, fused bias, direct to d_out) -------
__global__ __launch_bounds__(256, 2) void gemm_readout(
    const __half* __restrict__ A, const __half* __restrict__ B, float* __restrict__ C,
    int Nvalid, int K, int ldc, const float* __restrict__ bias)
{
    extern __shared__ __half smh[];
    float* smf = (float*)smh;
    int t = threadIdx.x;
    int m0 = blockIdx.y * BM, n0 = blockIdx.x * BN;
    int w = t >> 5, wm = w & 1, wn = w >> 1;
    int KT = K / HBK;

    CFH acc[4][2];
    #pragma unroll
    for (int i = 0; i < 4; i++)
        #pragma unroll
        for (int j = 0; j < 2; j++) wmma::fill_fragment(acc[i][j], 0.0f);

    h_issue(A, B, smh, t, m0, n0, K, Nvalid, 0, 0);
    h_issue(A, B, smh, t, m0, n0, K, Nvalid, 1, 1);

    for (int kt = 0; kt < KT; kt++) {
        if (kt == KT - 1) asm volatile("cp.async.wait_group 0;\n" ::: "memory");
        else              asm volatile("cp.async.wait_group 1;\n" ::: "memory");
        __syncthreads();
        if (kt + 2 < KT)
            h_issue(A, B, smh, t, m0, n0, K, Nvalid, kt + 2, (kt + 2) % 3);

        const __half* sa = smh + (kt % 3) * HSTRIDE;
        const __half* sb = sa + BM * HLDS;
        #pragma unroll
        for (int kk = 0; kk < HBK / 16; kk++) {
            AFH af[4]; BFH bf[2];
            #pragma unroll
            for (int i = 0; i < 4; i++)
                wmma::load_matrix_sync(af[i], sa + (wm * 64 + i * 16) * HLDS + kk * 16, HLDS);
            #pragma unroll
            for (int j = 0; j < 2; j++)
                wmma::load_matrix_sync(bf[j], sb + (wn * 32 + j * 16) * HLDS + kk * 16, HLDS);
            #pragma unroll
            for (int i = 0; i < 4; i++)
                #pragma unroll
                for (int j = 0; j < 2; j++)
                    wmma::mma_sync(acc[i][j], af[i], bf[j], acc[i][j]);
        }
    }

    __syncthreads();
    float* tile = smf;
    #pragma unroll
    for (int i = 0; i < 4; i++)
        #pragma unroll
        for (int j = 0; j < 2; j++)
            wmma::store_matrix_sync(tile + (wm * 64 + i * 16) * 132 + wn * 32 + j * 16,
                                    acc[i][j], 132, wmma::mem_row_major);
    __syncthreads();
    for (int idx = t; idx < BM * BN; idx += 256) {
        int r = idx >> 7, c = idx & 127;
        int col = n0 + c;
        if (col < Nvalid)
            C[(size_t)(m0 + r) * ldc + col] = tile[r * 132 + c] + bias[col];
    }
}

// ---------------- persistent middle v2: 128-row tiles, fp16 smem, 2 CTAs/SM --
#define MID_GRID 296
#define MTILES (BB * 2)                 // 8192 tiles of 128 rows
constexpr int MID_SMEM_BYTES = (2 * 128 * 72 + 3 * 64 * 72) * 2 + (256 + 64 + 64) * 4;  // 66048

__global__ __launch_bounds__(256, 2) void middle_kernel(
    const float* __restrict__ V_slow, const float* __restrict__ sem_mem,
    const float* __restrict__ mix_w, const float* __restrict__ mix_b,
    const float* __restrict__ q_w, const float* __restrict__ q_b)
{
    extern __shared__ __half smh_[];
    __half* hIn = smh_;                 // 128*72  agg -> y -> vp -> cell
    __half* hB  = hIn + 128 * 72;       // 128*72  v -> Q
    __half* hV  = hB + 128 * 72;        // 64*72
    __half* hS  = hV + 64 * 72;
    __half* hQ  = hS + 64 * 72;
    float* sKb = (float*)(hQ + 64 * 72);  // 256
    float* sqb = sKb + 256;               // 64
    float* smw = sqb + 64;                // 64

    int t = threadIdx.x;
    int w = t >> 5;
    int rb = (w >> 1) * 32;             // 4 row-blocks of 32 (128 rows)
    int cb = (w & 1) * 32;              // 2 col-blocks of 32
    int n2 = t >> 1, dh = (t & 1) * 32;

    for (int i = t; i < 64 * 64; i += 256) {
        int r = i >> 6, c2 = i & 63;
        hV[r * 72 + c2] = __float2half_rn(V_slow[i]);
        hS[r * 72 + c2] = __float2half_rn(sem_mem[i]);
        hQ[r * 72 + c2] = __float2half_rn(q_w[i]);
    }
    sKb[t] = g_K[t];
    if (t < 64) { sqb[t] = q_b[t]; smw[t] = mix_w[t]; }
    float mixb = mix_b[0];

    const float4* bp_ = (const float4*)g_bin2;

    int tile = blockIdx.x;
    uint4 pre[4];
    {
        const uint4* np_ = (const uint4*)(g_nodes_h + (size_t)tile * 128 * DD);
        #pragma unroll
        for (int j = 0; j < 4; j++) pre[j] = np_[t + j * 256];
    }

    while (tile < MTILES) {
        int ntile = tile + MID_GRID;
        int nb0 = (tile * 128) & (NN - 1);    // node base (0 or 128)
        __syncthreads();

        // agg(h) + bias -> hIn (fp16)
        #pragma unroll
        for (int j = 0; j < 4; j++) {
            int i = t + j * 256;              // uint4 idx, 8 halves each
            int r = i >> 3, d8 = (i & 7) * 8;
            const __half2* hp = (const __half2*)&pre[j];
            int bidx = (((nb0 + r) * DD + d8) >> 2);
            float4 b0 = bp_[bidx], b1 = bp_[bidx + 1];
            __half2* dst = (__half2*)&hIn[r * 72 + d8];
            float2 f0 = __half22float2(hp[0]);
            float2 f1 = __half22float2(hp[1]);
            float2 f2 = __half22float2(hp[2]);
            float2 f3 = __half22float2(hp[3]);
            dst[0] = __floats2half2_rn(f0.x + b0.x, f0.y + b0.y);
            dst[1] = __floats2half2_rn(f1.x + b0.z, f1.y + b0.w);
            dst[2] = __floats2half2_rn(f2.x + b1.x, f2.y + b1.y);
            dst[3] = __floats2half2_rn(f3.x + b1.z, f3.y + b1.w);
        }
        __syncthreads();

        // matmul1: v = clip(agg @ V^T), y = clip(agg @ S^T)  (fp16 results)
        CHH hv[2][2], hy[2][2];
        {
            CFH vf[2][2], yf[2][2];
            #pragma unroll
            for (int i = 0; i < 2; i++)
                #pragma unroll
                for (int j = 0; j < 2; j++) { wmma::fill_fragment(vf[i][j], 0.f); wmma::fill_fragment(yf[i][j], 0.f); }
            #pragma unroll
            for (int kk = 0; kk < 4; kk++) {
                AFH a0, a1; BFH bv0, bv1, bs0, bs1;
                wmma::load_matrix_sync(a0, &hIn[(rb     ) * 72 + kk * 16], 72);
                wmma::load_matrix_sync(a1, &hIn[(rb + 16) * 72 + kk * 16], 72);
                wmma::load_matrix_sync(bv0, &hV[(cb     ) * 72 + kk * 16], 72);
                wmma::load_matrix_sync(bv1, &hV[(cb + 16) * 72 + kk * 16], 72);
                wmma::load_matrix_sync(bs0, &hS[(cb     ) * 72 + kk * 16], 72);
                wmma::load_matrix_sync(bs1, &hS[(cb + 16) * 72 + kk * 16], 72);
                wmma::mma_sync(vf[0][0], a0, bv0, vf[0][0]);
                wmma::mma_sync(vf[0][1], a0, bv1, vf[0][1]);
                wmma::mma_sync(vf[1][0], a1, bv0, vf[1][0]);
                wmma::mma_sync(vf[1][1], a1, bv1, vf[1][1]);
                wmma::mma_sync(yf[0][0], a0, bs0, yf[0][0]);
                wmma::mma_sync(yf[0][1], a0, bs1, yf[0][1]);
                wmma::mma_sync(yf[1][0], a1, bs0, yf[1][0]);
                wmma::mma_sync(yf[1][1], a1, bs1, yf[1][1]);
            }
            #pragma unroll
            for (int i = 0; i < 2; i++)
                #pragma unroll
                for (int j = 0; j < 2; j++)
                    #pragma unroll
                    for (int e = 0; e < 8; e++) {
                        hv[i][j].x[e] = __float2half_rn(clip3(vf[i][j].x[e]));
                        hy[i][j].x[e] = __float2half_rn(clip3(yf[i][j].x[e]));
                    }
        }
        __syncthreads();   // all reads of agg (hIn) complete
        #pragma unroll
        for (int i = 0; i < 2; i++)
            #pragma unroll
            for (int j = 0; j < 2; j++) {
                wmma::store_matrix_sync(&hIn[(rb + i * 16) * 72 + cb + j * 16], hy[i][j], 72, wmma::mem_row_major);
                wmma::store_matrix_sync(&hB[(rb + i * 16) * 72 + cb + j * 16], hv[i][j], 72, wmma::mem_row_major);
            }
        __syncthreads();

        // mix = sigmoid(v . mix_w + mix_b)  (v fp16 from hB)
        float m;
        {
            const __half2* vp2 = (const __half2*)&hB[n2 * 72 + dh];
            float acc2 = 0.f;
            #pragma unroll
            for (int d = 0; d < 16; d++) {
                float2 f = __half22float2(vp2[d]);
                acc2 += f.x * smw[dh + d * 2] + f.y * smw[dh + d * 2 + 1];
            }
            acc2 += __shfl_xor_sync(0xffffffffu, acc2, 1);
            m = sigmoidf_(acc2 + mixb);
        }

        // matmul2: vp = clip(y(hIn) @ V^T) -> hIn (fp16)
        {
            CFH pf[2][2];
            #pragma unroll
            for (int i = 0; i < 2; i++)
                #pragma unroll
                for (int j = 0; j < 2; j++) wmma::fill_fragment(pf[i][j], 0.f);
            #pragma unroll
            for (int kk = 0; kk < 4; kk++) {
                AFH a0, a1; BFH bv0, bv1;
                wmma::load_matrix_sync(a0, &hIn[(rb     ) * 72 + kk * 16], 72);
                wmma::load_matrix_sync(a1, &hIn[(rb + 16) * 72 + kk * 16], 72);
                wmma::load_matrix_sync(bv0, &hV[(cb     ) * 72 + kk * 16], 72);
                wmma::load_matrix_sync(bv1, &hV[(cb + 16) * 72 + kk * 16], 72);
                wmma::mma_sync(pf[0][0], a0, bv0, pf[0][0]);
                wmma::mma_sync(pf[0][1], a0, bv1, pf[0][1]);
                wmma::mma_sync(pf[1][0], a1, bv0, pf[1][0]);
                wmma::mma_sync(pf[1][1], a1, bv1, pf[1][1]);
            }
            CHH hp[2][2];
            #pragma unroll
            for (int i = 0; i < 2; i++)
                #pragma unroll
                for (int j = 0; j < 2; j++)
                    #pragma unroll
                    for (int e = 0; e < 8; e++)
                        hp[i][j].x[e] = __float2half_rn(clip3(pf[i][j].x[e]));
            __syncthreads();   // all reads of y (hIn) complete
            #pragma unroll
            for (int i = 0; i < 2; i++)
                #pragma unroll
                for (int j = 0; j < 2; j++)
                    wmma::store_matrix_sync(&hIn[(rb + i * 16) * 72 + cb + j * 16], hp[i][j], 72, wmma::mem_row_major);
        }
        __syncthreads();

        // cell = fp16(clip(m*v + (1-m)*vp)) -> hIn (in place, own positions)
        {
            const __half2* vv = (const __half2*)&hB[n2 * 72 + dh];
            __half2* pp = (__half2*)&hIn[n2 * 72 + dh];
            #pragma unroll
            for (int d = 0; d < 16; d++) {
                float2 fv = __half22float2(vv[d]);
                float2 fp = __half22float2(pp[d]);
                pp[d] = __floats2half2_rn(clip3(m * fv.x + (1.f - m) * fp.x),
                                          clip3(m * fv.y + (1.f - m) * fp.y));
            }
        }
        __syncthreads();

        // matmul3: Q = cell(hIn) @ q_w^T -> hB (fp16)
        {
            CFH qf[2][2];
            #pragma unroll
            for (int i = 0; i < 2; i++)
                #pragma unroll
                for (int j = 0; j < 2; j++) wmma::fill_fragment(qf[i][j], 0.f);
            #pragma unroll
            for (int kk = 0; kk < 4; kk++) {
                AFH a0, a1; BFH bq0, bq1;
                wmma::load_matrix_sync(a0, &hIn[(rb     ) * 72 + kk * 16], 72);
                wmma::load_matrix_sync(a1, &hIn[(rb + 16) * 72 + kk * 16], 72);
                wmma::load_matrix_sync(bq0, &hQ[(cb     ) * 72 + kk * 16], 72);
                wmma::load_matrix_sync(bq1, &hQ[(cb + 16) * 72 + kk * 16], 72);
                wmma::mma_sync(qf[0][0], a0, bq0, qf[0][0]);
                wmma::mma_sync(qf[0][1], a0, bq1, qf[0][1]);
                wmma::mma_sync(qf[1][0], a1, bq0, qf[1][0]);
                wmma::mma_sync(qf[1][1], a1, bq1, qf[1][1]);
            }
            CHH hq[2][2];
            #pragma unroll
            for (int i = 0; i < 2; i++)
                #pragma unroll
                for (int j = 0; j < 2; j++) {
                    #pragma unroll
                    for (int e = 0; e < 8; e++)
                        hq[i][j].x[e] = __float2half_rn(qf[i][j].x[e]);
                    wmma::store_matrix_sync(&hB[(rb + i * 16) * 72 + cb + j * 16], hq[i][j], 72, wmma::mem_row_major);
                }
        }
        __syncthreads();

        // prefetch next tile (hidden under attention)
        if (ntile < MTILES) {
            const uint4* np_ = (const uint4*)(g_nodes_h + (size_t)ntile * 128 * DD);
            #pragma unroll
            for (int j = 0; j < 4; j++) pre[j] = np_[t + j * 256];
        }

        // attention: softmax -> g_wh (fp16)
        {
            const __half2* qp = (const __half2*)&hB[n2 * 72 + dh];
            float qv[32];
            #pragma unroll
            for (int d = 0; d < 16; d++) {
                float2 f = __half22float2(qp[d]);
                qv[d * 2]     = f.x + sqb[dh + d * 2];
                qv[d * 2 + 1] = f.y + sqb[dh + d * 2 + 1];
            }
            float s0 = 0.f, s1 = 0.f, s2 = 0.f, s3 = 0.f;
            #pragma unroll
            for (int d = 0; d < 32; d++) {
                s0 += qv[d] * sKb[dh + d];
                s1 += qv[d] * sKb[64 + dh + d];
                s2 += qv[d] * sKb[128 + dh + d];
                s3 += qv[d] * sKb[192 + dh + d];
            }
            s0 += __shfl_xor_sync(0xffffffffu, s0, 1);
            s1 += __shfl_xor_sync(0xffffffffu, s1, 1);
            s2 += __shfl_xor_sync(0xffffffffu, s2, 1);
            s3 += __shfl_xor_sync(0xffffffffu, s3, 1);
            if ((t & 1) == 0) {
                s0 *= 0.125f; s1 *= 0.125f; s2 *= 0.125f; s3 *= 0.125f;
                float mx = fmaxf(fmaxf(s0, s1), fmaxf(s2, s3));
                float e0 = expf(s0 - mx), e1 = expf(s1 - mx), e2 = expf(s2 - mx), e3 = expf(s3 - mx);
                float inv = 1.f / (e0 + e1 + e2 + e3);
                __half2* dst = (__half2*)(g_wh + ((size_t)tile * 128 + n2) * 4);
                dst[0] = __floats2half2_rn(e0 * inv, e1 * inv);
                dst[1] = __floats2half2_rn(e2 * inv, e3 * inv);
            }
        }

        tile = ntile;
    }
}

// ---------------- launcher ---------------------------------------------------
extern "C" void kernel_launch(void* const* d_in, const int* in_sizes, int n_in,
                              void* d_out, int out_size)
{
    (void)in_sizes; (void)n_in; (void)out_size;
    const float* x      = (const float*)d_in[0];
    const float* W_in   = (const float*)d_in[1];
    const float* b_in   = (const float*)d_in[2];
    const float* adj_w  = (const float*)d_in[3];
    const float* V_slow = (const float*)d_in[5];
    const float* sem    = (const float*)d_in[6];
    const float* mix_w  = (const float*)d_in[7];
    const float* mix_b  = (const float*)d_in[8];
    const float* basis  = (const float*)d_in[9];
    const float* q_w    = (const float*)d_in[10];
    const float* q_b    = (const float*)d_in[11];
    const float* k_w    = (const float*)d_in[12];
    const float* k_b    = (const float*)d_in[13];
    const float* W_out  = (const float*)d_in[14];
    const float* b_out  = (const float*)d_in[15];
    float* out = (float*)d_out;

    cudaFuncSetAttribute(gemm1_h,      cudaFuncAttributeMaxDynamicSharedMemorySize, GEMM_SMEM_H);
    cudaFuncSetAttribute(gemm_readout, cudaFuncAttributeMaxDynamicSharedMemorySize, GEMM_SMEM_H);
    cudaFuncSetAttribute(middle_kernel, cudaFuncAttributeMaxDynamicSharedMemorySize, MID_SMEM_BYTES);

    void *p_nodes = 0, *p_wh = 0, *p_mmath = 0, *p_win2h = 0, *p_xh = 0;
    cudaGetSymbolAddress(&p_nodes,  g_nodes_h);
    cudaGetSymbolAddress(&p_wh,     g_wh);
    cudaGetSymbolAddress(&p_mmath,  g_mmath);
    cudaGetSymbolAddress(&p_win2h,  g_win2h);
    cudaGetSymbolAddress(&p_xh,     g_xh);

    prep_kernel<<<1, 256>>>(adj_w, k_w, k_b, basis);
    prep2_kernel<<<PREP2_GRID, 256>>>(W_in, b_in, x, W_out, basis);

    // agg = xh @ W_in'^T  (fp16 MMA, direct fp16 store)
    gemm1_h<<<dim3(HH / BN, BB / BM), 256, GEMM_SMEM_H>>>(
        (const __half*)p_xh, (const __half*)p_win2h, (__half*)p_nodes);

    // persistent middle (fp16 smem, 128-row tiles, 2 CTAs/SM)
    middle_kernel<<<MID_GRID, 256, MID_SMEM_BYTES>>>(V_slow, sem, mix_w, mix_b, q_w, q_b);

    // logits = wh @ Mmat^T + b_out  (fp16 MMA, direct store to d_out)
    gemm_readout<<<dim3(CPAD / BN, BB / BM), 256, GEMM_SMEM_H>>>(
        (const __half*)p_wh, (const __half*)p_mmath, out, CC, CPAD, CC, b_out);
}